// round 1
// baseline (speedup 1.0000x reference)
#include <cuda_runtime.h>
#include <math.h>

#define BATCH 16
#define INDIM 512
#define MIDC  256
#define HW    4096
#define HEADS 8

// ---------------- scratch (device globals; no allocation) ----------------
__device__ float g_buf1[BATCH*MIDC*HW];   // xr0 (pre-dw), later attn frequency output
__device__ float g_xr  [BATCH*MIDC*HW];   // post dw+BN+ReLU
__device__ float g_Fr  [BATCH*MIDC*HW];   // fft_feat real (ortho, bitrev order)
__device__ float g_Fi  [BATCH*MIDC*HW];   // fft_feat imag
__device__ float g_fused[BATCH*INDIM*HW]; // [out | fwm]
__device__ float g_means[BATCH*MIDC];
__device__ float g_nrm  [BATCH*MIDC];
__device__ float g_gate [BATCH*MIDC];

// ---------------- FFT helpers (64-pt radix-2, in-place, smem) ----------------
// forward: DIF, natural in -> bit-reversed out, twiddle e^{-2pi i k/64}
// inverse: DIT, bit-reversed in -> natural out (unscaled IDFT)
__device__ __forceinline__ void fft_load_tw(float* twr, float* twi, int tid) {
    if (tid < 32) {
        float s, c;
        sincosf(-6.28318530717958647692f * (float)tid * (1.0f/64.0f), &s, &c);
        twr[tid] = c; twi[tid] = s;
    }
}

__device__ __forceinline__ void fft_dif(float* Ar, float* Ai,
                                        const float* twr, const float* twi,
                                        int tid, bool col) {
    int mult = 1;
    for (int s = 32; s >= 1; s >>= 1, mult <<= 1) {
#pragma unroll
        for (int i = 0; i < 8; i++) {
            int t = tid + (i << 8);
            int line = t >> 5, q = t & 31;
            int p  = q & (s - 1);
            int i0 = 2*q - p, i1 = i0 + s;
            int a0 = col ? (i0*65 + line) : (line*65 + i0);
            int a1 = col ? (i1*65 + line) : (line*65 + i1);
            float ur = Ar[a0], ui = Ai[a0];
            float vr = Ar[a1], vi = Ai[a1];
            int ti2 = p * mult;
            float wr = twr[ti2], wi = twi[ti2];
            Ar[a0] = ur + vr; Ai[a0] = ui + vi;
            float dr = ur - vr, di = ui - vi;
            Ar[a1] = dr*wr - di*wi;
            Ai[a1] = dr*wi + di*wr;
        }
        __syncthreads();
    }
}

__device__ __forceinline__ void fft_dit(float* Ar, float* Ai,
                                        const float* twr, const float* twi,
                                        int tid, bool col) {
    int mult = 32;
    for (int s = 1; s <= 32; s <<= 1, mult >>= 1) {
#pragma unroll
        for (int i = 0; i < 8; i++) {
            int t = tid + (i << 8);
            int line = t >> 5, q = t & 31;
            int p  = q & (s - 1);
            int i0 = 2*q - p, i1 = i0 + s;
            int a0 = col ? (i0*65 + line) : (line*65 + i0);
            int a1 = col ? (i1*65 + line) : (line*65 + i1);
            int ti2 = p * mult;
            float wr = twr[ti2], wi = -twi[ti2];   // conjugate
            float ur = Ar[a0], ui = Ai[a0];
            float vr = Ar[a1], vi = Ai[a1];
            float tr = vr*wr - vi*wi;
            float tq = vr*wi + vi*wr;
            Ar[a0] = ur + tr; Ai[a0] = ui + tq;
            Ar[a1] = ur - tr; Ai[a1] = ui - tq;
        }
        __syncthreads();
    }
}

// ---------------- K1/K8: SGEMM 128x128x16, 8x8 per thread ----------------
__device__ __forceinline__ void gemm_body(const float* __restrict__ A,
                                          const float* __restrict__ Bp,
                                          int K, int mb, int nb,
                                          float acc[8][8]) {
    __shared__ float As[16][128];
    __shared__ float Bs[16][128];
    const int N = HW;
    int tid = threadIdx.x;
    int ar = tid >> 2;           // 0..63
    int ac = (tid & 3) << 2;     // 0,4,8,12
    int br = tid >> 5;           // 0..7
    int bc = (tid & 31) << 2;    // 0..124
    int m0 = (tid >> 4) << 3;
    int n0 = (tid & 15) << 3;
    for (int kb = 0; kb < K; kb += 16) {
        float4 a0 = *(const float4*)(A + (size_t)(mb + ar)      * K + kb + ac);
        float4 a1 = *(const float4*)(A + (size_t)(mb + ar + 64) * K + kb + ac);
        float4 b0 = *(const float4*)(Bp + (size_t)(kb + br)     * N + nb + bc);
        float4 b1 = *(const float4*)(Bp + (size_t)(kb + br + 8) * N + nb + bc);
        As[ac+0][ar] = a0.x; As[ac+1][ar] = a0.y; As[ac+2][ar] = a0.z; As[ac+3][ar] = a0.w;
        As[ac+0][ar+64] = a1.x; As[ac+1][ar+64] = a1.y; As[ac+2][ar+64] = a1.z; As[ac+3][ar+64] = a1.w;
        *(float4*)&Bs[br][bc]   = b0;
        *(float4*)&Bs[br+8][bc] = b1;
        __syncthreads();
#pragma unroll
        for (int k = 0; k < 16; k++) {
            float a[8], b[8];
            *(float4*)&a[0] = *(const float4*)&As[k][m0];
            *(float4*)&a[4] = *(const float4*)&As[k][m0+4];
            *(float4*)&b[0] = *(const float4*)&Bs[k][n0];
            *(float4*)&b[4] = *(const float4*)&Bs[k][n0+4];
#pragma unroll
            for (int im = 0; im < 8; im++)
#pragma unroll
                for (int in = 0; in < 8; in++)
                    acc[im][in] += a[im]*b[in];
        }
        __syncthreads();
    }
}

__global__ void __launch_bounds__(256) k_gemm_reduce(const float* __restrict__ W,
                                                     const float* __restrict__ X,
                                                     const float* __restrict__ bias) {
    int b  = blockIdx.z;
    int mb = blockIdx.y * 128, nb = blockIdx.x * 128;
    float acc[8][8];
#pragma unroll
    for (int i = 0; i < 8; i++)
#pragma unroll
        for (int j = 0; j < 8; j++) acc[i][j] = 0.f;
    gemm_body(W, X + (size_t)b*INDIM*HW, INDIM, mb, nb, acc);
    int m0 = (threadIdx.x >> 4) << 3, n0 = (threadIdx.x & 15) << 3;
    float* C = g_buf1 + (size_t)b*MIDC*HW;
#pragma unroll
    for (int im = 0; im < 8; im++) {
        int row = mb + m0 + im;
        float bi = bias[row];
        float4 v0 = make_float4(acc[im][0]+bi, acc[im][1]+bi, acc[im][2]+bi, acc[im][3]+bi);
        float4 v1 = make_float4(acc[im][4]+bi, acc[im][5]+bi, acc[im][6]+bi, acc[im][7]+bi);
        *(float4*)(C + (size_t)row*HW + nb + n0)     = v0;
        *(float4*)(C + (size_t)row*HW + nb + n0 + 4) = v1;
    }
}

__global__ void __launch_bounds__(256) k_gemm_post(const float* __restrict__ W,
                                                   const float* __restrict__ bias,
                                                   const float* __restrict__ xres,
                                                   float* __restrict__ out) {
    int b  = blockIdx.z;
    int mb = blockIdx.y * 128, nb = blockIdx.x * 128;
    float acc[8][8];
#pragma unroll
    for (int i = 0; i < 8; i++)
#pragma unroll
        for (int j = 0; j < 8; j++) acc[i][j] = 0.f;
    gemm_body(W, g_fused + (size_t)b*INDIM*HW, INDIM, mb, nb, acc);
    int m0 = (threadIdx.x >> 4) << 3, n0 = (threadIdx.x & 15) << 3;
    float* C = out + (size_t)b*INDIM*HW;
    const float* Xr = xres + (size_t)b*INDIM*HW;
#pragma unroll
    for (int im = 0; im < 8; im++) {
        int row = mb + m0 + im;
        float bi = bias[row];
        size_t off = (size_t)row*HW + nb + n0;
        float4 r0 = *(const float4*)(Xr + off);
        float4 r1 = *(const float4*)(Xr + off + 4);
        float4 v0 = make_float4(acc[im][0]+bi+r0.x, acc[im][1]+bi+r0.y, acc[im][2]+bi+r0.z, acc[im][3]+bi+r0.w);
        float4 v1 = make_float4(acc[im][4]+bi+r1.x, acc[im][5]+bi+r1.y, acc[im][6]+bi+r1.z, acc[im][7]+bi+r1.w);
        *(float4*)(C + off)     = v0;
        *(float4*)(C + off + 4) = v1;
    }
}

// ---------------- K2: depthwise 3x3 + bias + BN + ReLU + stats ----------------
__global__ void __launch_bounds__(256) k_dw(const float* __restrict__ dww,
                                            const float* __restrict__ dwb,
                                            const float* __restrict__ gamma,
                                            const float* __restrict__ beta,
                                            const float* __restrict__ mean,
                                            const float* __restrict__ var) {
    int plane = blockIdx.x;
    int c = plane & (MIDC-1);
    __shared__ float tile[66*66];
    const float* src = g_buf1 + (size_t)plane*HW;
    for (int idx = threadIdx.x; idx < 66*66; idx += 256) {
        int r = idx / 66, cc = idx - r*66;
        int y = r - 1, x = cc - 1;
        float v = 0.f;
        if ((unsigned)y < 64u && (unsigned)x < 64u) v = src[y*64 + x];
        tile[idx] = v;
    }
    __syncthreads();
    float w0 = dww[c*9+0], w1 = dww[c*9+1], w2 = dww[c*9+2];
    float w3 = dww[c*9+3], w4 = dww[c*9+4], w5 = dww[c*9+5];
    float w6 = dww[c*9+6], w7 = dww[c*9+7], w8 = dww[c*9+8];
    float scale = gamma[c] * rsqrtf(var[c] + 1e-5f);
    float shift = beta[c] - mean[c]*scale;
    float bia = dwb[c];
    float s = 0.f, sq = 0.f;
    float* dst = g_xr + (size_t)plane*HW;
#pragma unroll
    for (int i = 0; i < 16; i++) {
        int p = threadIdx.x + i*256;
        int py = p >> 6, px = p & 63;
        const float* t0 = &tile[py*66 + px];
        float acc = t0[0]*w0 + t0[1]*w1 + t0[2]*w2
                  + t0[66]*w3 + t0[67]*w4 + t0[68]*w5
                  + t0[132]*w6 + t0[133]*w7 + t0[134]*w8;
        acc = fmaxf((acc + bia)*scale + shift, 0.f);
        dst[p] = acc;
        s += acc; sq += acc*acc;
    }
#pragma unroll
    for (int o = 16; o; o >>= 1) {
        s  += __shfl_xor_sync(0xffffffffu, s,  o);
        sq += __shfl_xor_sync(0xffffffffu, sq, o);
    }
    __shared__ float rs[8], rq[8];
    int wid = threadIdx.x >> 5;
    if ((threadIdx.x & 31) == 0) { rs[wid] = s; rq[wid] = sq; }
    __syncthreads();
    if (threadIdx.x == 0) {
        float ts = 0.f, tq = 0.f;
#pragma unroll
        for (int w = 0; w < 8; w++) { ts += rs[w]; tq += rq[w]; }
        g_means[plane] = ts * (1.f/4096.f);
        g_nrm[plane]   = sqrtf(tq);          // Parseval: ||F||2 == ||xr||2 (ortho)
    }
}

// ---------------- K3: SE gate MLP ----------------
__global__ void __launch_bounds__(256) k_gate(const float* __restrict__ w1,
                                              const float* __restrict__ b1,
                                              const float* __restrict__ w2,
                                              const float* __restrict__ b2) {
    int b = blockIdx.x;
    __shared__ float sm[MIDC];
    __shared__ float sh[32];
    int tid = threadIdx.x;
    sm[tid] = g_means[b*MIDC + tid];
    __syncthreads();
    if (tid < 32) {
        float a = b1[tid];
        const float* wr = w1 + tid*MIDC;
        for (int c2 = 0; c2 < MIDC; c2++) a += wr[c2]*sm[c2];
        sh[tid] = fmaxf(a, 0.f);
    }
    __syncthreads();
    float a = b2[tid];
    const float* wr = w2 + tid*32;
#pragma unroll
    for (int j = 0; j < 32; j++) a += wr[j]*sh[j];
    g_gate[b*MIDC + tid] = 1.f / (1.f + expf(-a));
}

// ---------------- K4: forward FFT (ortho) -> Fr,Fi (bitrev order) ----------------
__global__ void __launch_bounds__(256) k_fft_fwd() {
    __shared__ float Ar[64*65], Ai[64*65], twr[32], twi[32];
    int plane = blockIdx.x, tid = threadIdx.x;
    const float* src = g_xr + (size_t)plane*HW;
#pragma unroll
    for (int i = 0; i < 16; i++) {
        int p = tid + i*256; int r = p >> 6, c = p & 63;
        Ar[r*65+c] = src[p]; Ai[r*65+c] = 0.f;
    }
    fft_load_tw(twr, twi, tid);
    __syncthreads();
    fft_dif(Ar, Ai, twr, twi, tid, false);
    fft_dif(Ar, Ai, twr, twi, tid, true);
    float* fr = g_Fr + (size_t)plane*HW;
    float* fi = g_Fi + (size_t)plane*HW;
#pragma unroll
    for (int i = 0; i < 16; i++) {
        int p = tid + i*256; int r = p >> 6, c = p & 63;
        fr[p] = Ar[r*65+c] * (1.f/64.f);
        fi[p] = Ai[r*65+c] * (1.f/64.f);
    }
}

// ---------------- K5: FFT channel attention ----------------
__global__ void __launch_bounds__(256) k_attn(const float* __restrict__ temp) {
    int h = blockIdx.x, b = blockIdx.y;
    size_t base = ((size_t)b*MIDC + h*32) * HW;
    __shared__ float sFr[32][65], sFi[32][65];
    __shared__ float sM[32][33], sA[32][33], sN[32];
    int tid = threadIdx.x;
    int c0 = (tid >> 4) * 2, d0 = (tid & 15) * 2;
    float a00 = 0.f, a01 = 0.f, a10 = 0.f, a11 = 0.f;
    for (int n0 = 0; n0 < HW; n0 += 64) {
        __syncthreads();
        for (int idx = tid; idx < 32*64; idx += 256) {
            int cc = idx >> 6, nn = idx & 63;
            sFr[cc][nn] = g_Fr[base + (size_t)cc*HW + n0 + nn];
            sFi[cc][nn] = g_Fi[base + (size_t)cc*HW + n0 + nn];
        }
        __syncthreads();
#pragma unroll 4
        for (int nn = 0; nn < 64; nn++) {
            float rc0 = sFr[c0][nn],   rc1 = sFr[c0+1][nn];
            float rd0 = sFr[d0][nn],   rd1 = sFr[d0+1][nn];
            float ic0 = sFi[c0][nn],   ic1 = sFi[c0+1][nn];
            float id0 = sFi[d0][nn],   id1 = sFi[d0+1][nn];
            a00 += rc0*rd0 - ic0*id0;
            a01 += rc0*rd1 - ic0*id1;
            a10 += rc1*rd0 - ic1*id0;
            a11 += rc1*rd1 - ic1*id1;
        }
    }
    if (tid < 32) sN[tid] = fmaxf(g_nrm[b*MIDC + h*32 + tid], 1e-12f);
    __syncthreads();
    float tK = temp[h];
    sM[c0  ][d0  ] = a00 * tK / (sN[c0  ]*sN[d0  ]);
    sM[c0  ][d0+1] = a01 * tK / (sN[c0  ]*sN[d0+1]);
    sM[c0+1][d0  ] = a10 * tK / (sN[c0+1]*sN[d0  ]);
    sM[c0+1][d0+1] = a11 * tK / (sN[c0+1]*sN[d0+1]);
    __syncthreads();
    int lane = tid & 31;
#pragma unroll
    for (int rr = 0; rr < 4; rr++) {
        int row = (tid >> 5)*4 + rr;
        float v = sM[row][lane];
        float mx = v;
#pragma unroll
        for (int o = 16; o; o >>= 1) mx = fmaxf(mx, __shfl_xor_sync(0xffffffffu, mx, o));
        float e = expf(v - mx);
        float sm = e;
#pragma unroll
        for (int o = 16; o; o >>= 1) sm += __shfl_xor_sync(0xffffffffu, sm, o);
        sA[row][lane] = e / sm;
    }
    // out[c,n] = sum_d attn[c,d] * Fr[d,n]
    for (int n0 = 0; n0 < HW; n0 += 64) {
        __syncthreads();
        for (int idx = tid; idx < 32*64; idx += 256) {
            int cc = idx >> 6, nn = idx & 63;
            sFr[cc][nn] = g_Fr[base + (size_t)cc*HW + n0 + nn];
        }
        __syncthreads();
#pragma unroll
        for (int i = 0; i < 8; i++) {
            int idx = tid + i*256;
            int cc = idx >> 6, nn = idx & 63;
            float acc = 0.f;
#pragma unroll
            for (int d = 0; d < 32; d++) acc += sA[cc][d] * sFr[d][nn];
            g_buf1[base + (size_t)cc*HW + n0 + nn] = acc;
        }
    }
}

// ---------------- K6: inverse FFT (ortho) of attn branch -> fused[:, 0:256] ----------------
__global__ void __launch_bounds__(256) k_ifft_attn() {
    __shared__ float Ar[64*65], Ai[64*65], twr[32], twi[32];
    int plane = blockIdx.x, tid = threadIdx.x;
    int b = plane >> 8, c = plane & (MIDC-1);
    const float* src = g_buf1 + (size_t)plane*HW;
#pragma unroll
    for (int i = 0; i < 16; i++) {
        int p = tid + i*256; int r = p >> 6, cc = p & 63;
        Ar[r*65+cc] = src[p]; Ai[r*65+cc] = 0.f;
    }
    fft_load_tw(twr, twi, tid);
    __syncthreads();
    fft_dit(Ar, Ai, twr, twi, tid, false);
    fft_dit(Ar, Ai, twr, twi, tid, true);
    float* dst = g_fused + ((size_t)b*INDIM + c)*HW;
#pragma unroll
    for (int i = 0; i < 16; i++) {
        int p = tid + i*256; int r = p >> 6, cc = p & 63;
        dst[p] = Ar[r*65+cc] * (1.f/64.f);   // ortho ifft2 = IDFT_unscaled/64
    }
}

// ---------------- K7: fwm = ifft2( fft_feat * fft2(g*xr) ).real -> fused[:, 256:512] ----------------
__global__ void __launch_bounds__(256) k_fwm() {
    __shared__ float Ar[64*65], Ai[64*65], twr[32], twi[32];
    int plane = blockIdx.x, tid = threadIdx.x;
    int b = plane >> 8, c = plane & (MIDC-1);
    float gv = g_gate[b*MIDC + c];
    const float* src = g_xr + (size_t)plane*HW;
#pragma unroll
    for (int i = 0; i < 16; i++) {
        int p = tid + i*256; int r = p >> 6, cc = p & 63;
        Ar[r*65+cc] = gv * src[p]; Ai[r*65+cc] = 0.f;
    }
    fft_load_tw(twr, twi, tid);
    __syncthreads();
    fft_dif(Ar, Ai, twr, twi, tid, false);   // forward, unscaled (default fft2 norm)
    fft_dif(Ar, Ai, twr, twi, tid, true);
    const float* fr = g_Fr + (size_t)plane*HW;
    const float* fi = g_Fi + (size_t)plane*HW;
#pragma unroll
    for (int i = 0; i < 16; i++) {
        int p = tid + i*256; int r = p >> 6, cc = p & 63;
        int a = r*65 + cc;
        float xr_ = Ar[a], xi_ = Ai[a];
        float yr = fr[p], yi = fi[p];
        Ar[a] = xr_*yr - xi_*yi;
        Ai[a] = xr_*yi + xi_*yr;
    }
    __syncthreads();
    fft_dit(Ar, Ai, twr, twi, tid, false);
    fft_dit(Ar, Ai, twr, twi, tid, true);
    float* dst = g_fused + ((size_t)b*INDIM + MIDC + c)*HW;
#pragma unroll
    for (int i = 0; i < 16; i++) {
        int p = tid + i*256; int r = p >> 6, cc = p & 63;
        dst[p] = Ar[r*65+cc] * (1.f/4096.f); // default ifft2 norm
    }
}

// ---------------- launch ----------------
extern "C" void kernel_launch(void* const* d_in, const int* in_sizes, int n_in,
                              void* d_out, int out_size) {
    (void)in_sizes; (void)n_in; (void)out_size;
    const float* x        = (const float*)d_in[0];
    const float* reduce_w = (const float*)d_in[1];
    const float* reduce_b = (const float*)d_in[2];
    const float* dw_w     = (const float*)d_in[3];
    const float* dw_b     = (const float*)d_in[4];
    const float* bn_gamma = (const float*)d_in[5];
    const float* bn_beta  = (const float*)d_in[6];
    const float* bn_mean  = (const float*)d_in[7];
    const float* bn_var   = (const float*)d_in[8];
    const float* gate_w1  = (const float*)d_in[9];
    const float* gate_b1  = (const float*)d_in[10];
    const float* gate_w2  = (const float*)d_in[11];
    const float* gate_b2  = (const float*)d_in[12];
    const float* temp     = (const float*)d_in[13];
    const float* post_w   = (const float*)d_in[14];
    const float* post_b   = (const float*)d_in[15];
    float* out = (float*)d_out;

    k_gemm_reduce<<<dim3(32, 2, BATCH), 256>>>(reduce_w, x, reduce_b);
    k_dw<<<BATCH*MIDC, 256>>>(dw_w, dw_b, bn_gamma, bn_beta, bn_mean, bn_var);
    k_gate<<<BATCH, 256>>>(gate_w1, gate_b1, gate_w2, gate_b2);
    k_fft_fwd<<<BATCH*MIDC, 256>>>();
    k_attn<<<dim3(HEADS, BATCH), 256>>>(temp);
    k_ifft_attn<<<BATCH*MIDC, 256>>>();
    k_fwm<<<BATCH*MIDC, 256>>>();
    k_gemm_post<<<dim3(32, 4, BATCH), 256>>>(post_w, post_b, x, out);
}

// round 3
// speedup vs baseline: 1.5677x; 1.5677x over previous
#include <cuda_runtime.h>
#include <cuda_bf16.h>
#include <mma.h>
#include <math.h>
#include <stdint.h>

using namespace nvcuda;

#define BATCH 16
#define INDIM 512
#define MIDC  256
#define HW    4096
#define HEADS 8

// ---------------- scratch (device globals; no allocation) ----------------
__device__ float g_buf1[BATCH*MIDC*HW];   // xr0 (pre-dw), later attn frequency output
__device__ float g_xr  [BATCH*MIDC*HW];   // post dw+BN+ReLU
__device__ float g_Fr  [BATCH*MIDC*HW];   // fft_feat real (ortho, bitrev order)
__device__ float g_Fi  [BATCH*MIDC*HW];   // fft_feat imag
__device__ float g_means[BATCH*MIDC];
__device__ float g_nrm  [BATCH*MIDC];
__device__ float g_gate [BATCH*MIDC];
// bf16 operands for tensor-core GEMMs
__device__ __nv_bfloat16 g_x_bf    [BATCH*INDIM*HW];  // x in bf16
__device__ __nv_bfloat16 g_fused_bf[BATCH*INDIM*HW];  // [attn_out | fwm] bf16
__device__ __nv_bfloat16 g_wred    [MIDC*INDIM];
__device__ __nv_bfloat16 g_wpost   [INDIM*2*MIDC];

// ================= wmma bf16 GEMM =================
// C[Mtot,4096] = W[Mtot,512] * act[512,4096] (+bias)(+resid), per batch z.
// CTA tile 128x128, K-chunk 32. 8 warps, warp tile 32x64 (2x4 wmma frags).
#define AS_STRIDE 40    // 32 + 8 pad (bf16)
#define BS_STRIDE 136   // 128 + 8 pad (bf16)
#define CS_STRIDE 132   // 128 + 4 pad (f32)
#define GEMM_SMEM (128*CS_STRIDE*4)   // 67584 B (C staging; A/B overlap inside)

__global__ void __launch_bounds__(256)
k_wmma_gemm(const __nv_bfloat16* __restrict__ W,
            const __nv_bfloat16* __restrict__ act,   // [B][512][4096]
            const float* __restrict__ bias,
            const float* __restrict__ resid,         // may be null
            float* __restrict__ out,                 // [B][Mtot][4096]
            int Mtot) {
    extern __shared__ char sm[];
    __nv_bfloat16* As = (__nv_bfloat16*)sm;                       // [128][AS_STRIDE]
    __nv_bfloat16* Bs = (__nv_bfloat16*)(sm + 128*AS_STRIDE*2);   // [32][BS_STRIDE]
    float*         Cs = (float*)sm;                               // [128][CS_STRIDE]

    int tid = threadIdx.x;
    int w   = tid >> 5;
    int wm  = w & 3;          // 4 warps over M (32 rows each)
    int wn  = w >> 2;         // 2 warps over N (64 cols each)
    int nb = blockIdx.x * 128, mb = blockIdx.y * 128, b = blockIdx.z;

    const __nv_bfloat16* Ag = W + (size_t)mb * 512;
    const __nv_bfloat16* Bg = act + (size_t)b * 512 * 4096 + nb;

    wmma::fragment<wmma::accumulator, 16, 16, 16, float> acc[2][4];
#pragma unroll
    for (int i = 0; i < 2; i++)
#pragma unroll
        for (int j = 0; j < 4; j++) wmma::fill_fragment(acc[i][j], 0.0f);

    for (int kc = 0; kc < 512; kc += 32) {
        __syncthreads();
        // A: 128x32 -> 512 uint4, thread loads id=tid, tid+256
#pragma unroll
        for (int t = 0; t < 2; t++) {
            int id = tid + t * 256;
            int r = id >> 2, c8 = (id & 3) * 8;
            uint4 v = *(const uint4*)(Ag + (size_t)r * 512 + kc + c8);
            *(uint4*)(As + r * AS_STRIDE + c8) = v;
        }
        // B: 32x128 -> 512 uint4
#pragma unroll
        for (int t = 0; t < 2; t++) {
            int id = tid + t * 256;
            int r = id >> 4, c8 = (id & 15) * 8;
            uint4 v = *(const uint4*)(Bg + (size_t)(kc + r) * 4096 + c8);
            *(uint4*)(Bs + r * BS_STRIDE + c8) = v;
        }
        __syncthreads();
#pragma unroll
        for (int ks = 0; ks < 2; ks++) {
            wmma::fragment<wmma::matrix_a, 16, 16, 16, __nv_bfloat16, wmma::row_major> af[2];
            wmma::fragment<wmma::matrix_b, 16, 16, 16, __nv_bfloat16, wmma::row_major> bf[4];
#pragma unroll
            for (int i = 0; i < 2; i++)
                wmma::load_matrix_sync(af[i], As + (wm*32 + i*16) * AS_STRIDE + ks*16, AS_STRIDE);
#pragma unroll
            for (int j = 0; j < 4; j++)
                wmma::load_matrix_sync(bf[j], Bs + (ks*16) * BS_STRIDE + wn*64 + j*16, BS_STRIDE);
#pragma unroll
            for (int i = 0; i < 2; i++)
#pragma unroll
                for (int j = 0; j < 4; j++)
                    wmma::mma_sync(acc[i][j], af[i], bf[j], acc[i][j]);
        }
    }
    __syncthreads();
    // stage C in smem (disjoint per warp)
#pragma unroll
    for (int i = 0; i < 2; i++)
#pragma unroll
        for (int j = 0; j < 4; j++)
            wmma::store_matrix_sync(Cs + (wm*32 + i*16) * CS_STRIDE + wn*64 + j*16,
                                    acc[i][j], CS_STRIDE, wmma::mem_row_major);
    __syncthreads();
    // epilogue: bias + optional residual, float4 stores
#pragma unroll
    for (int t = 0; t < 16; t++) {
        int id = tid + t * 256;          // 4096 float4 total
        int r = id >> 5, c = (id & 31) * 4;
        float bi = bias ? bias[mb + r] : 0.0f;
        float4 v = *(float4*)(Cs + r * CS_STRIDE + c);
        v.x += bi; v.y += bi; v.z += bi; v.w += bi;
        size_t off = ((size_t)b * Mtot + mb + r) * 4096 + nb + c;
        if (resid) {
            float4 rr = *(const float4*)(resid + off);
            v.x += rr.x; v.y += rr.y; v.z += rr.z; v.w += rr.w;
        }
        *(float4*)(out + off) = v;
    }
}

// ---------------- conversion ----------------
__global__ void __launch_bounds__(256) k_cvt(const float* __restrict__ src,
                                             __nv_bfloat16* __restrict__ dst, int n) {
    int i = (blockIdx.x * 256 + threadIdx.x) * 4;
    if (i < n) {
        float4 v = *(const float4*)(src + i);
        __nv_bfloat162 p0 = __floats2bfloat162_rn(v.x, v.y);
        __nv_bfloat162 p1 = __floats2bfloat162_rn(v.z, v.w);
        uint2 pk;
        pk.x = *(uint32_t*)&p0; pk.y = *(uint32_t*)&p1;
        *(uint2*)(dst + i) = pk;
    }
}

// ---------------- FFT helpers (64-pt radix-2, in-place, smem) ----------------
__device__ __forceinline__ void fft_load_tw(float* twr, float* twi, int tid) {
    if (tid < 32) {
        float s, c;
        sincosf(-6.28318530717958647692f * (float)tid * (1.0f/64.0f), &s, &c);
        twr[tid] = c; twi[tid] = s;
    }
}

__device__ __forceinline__ void fft_dif(float* Ar, float* Ai,
                                        const float* twr, const float* twi,
                                        int tid, bool col) {
    int mult = 1;
    for (int s = 32; s >= 1; s >>= 1, mult <<= 1) {
#pragma unroll
        for (int i = 0; i < 8; i++) {
            int t = tid + (i << 8);
            int line = t >> 5, q = t & 31;
            int p  = q & (s - 1);
            int i0 = 2*q - p, i1 = i0 + s;
            int a0 = col ? (i0*65 + line) : (line*65 + i0);
            int a1 = col ? (i1*65 + line) : (line*65 + i1);
            float ur = Ar[a0], ui = Ai[a0];
            float vr = Ar[a1], vi = Ai[a1];
            int ti2 = p * mult;
            float wr = twr[ti2], wi = twi[ti2];
            Ar[a0] = ur + vr; Ai[a0] = ui + vi;
            float dr = ur - vr, di = ui - vi;
            Ar[a1] = dr*wr - di*wi;
            Ai[a1] = dr*wi + di*wr;
        }
        __syncthreads();
    }
}

__device__ __forceinline__ void fft_dit(float* Ar, float* Ai,
                                        const float* twr, const float* twi,
                                        int tid, bool col) {
    int mult = 32;
    for (int s = 1; s <= 32; s <<= 1, mult >>= 1) {
#pragma unroll
        for (int i = 0; i < 8; i++) {
            int t = tid + (i << 8);
            int line = t >> 5, q = t & 31;
            int p  = q & (s - 1);
            int i0 = 2*q - p, i1 = i0 + s;
            int a0 = col ? (i0*65 + line) : (line*65 + i0);
            int a1 = col ? (i1*65 + line) : (line*65 + i1);
            int ti2 = p * mult;
            float wr = twr[ti2], wi = -twi[ti2];   // conjugate
            float ur = Ar[a0], ui = Ai[a0];
            float vr = Ar[a1], vi = Ai[a1];
            float tr = vr*wr - vi*wi;
            float tq = vr*wi + vi*wr;
            Ar[a0] = ur + tr; Ai[a0] = ui + tq;
            Ar[a1] = ur - tr; Ai[a1] = ui - tq;
        }
        __syncthreads();
    }
}

// ---------------- K2: depthwise 3x3 + bias + BN + ReLU + stats ----------------
__global__ void __launch_bounds__(256) k_dw(const float* __restrict__ dww,
                                            const float* __restrict__ dwb,
                                            const float* __restrict__ gamma,
                                            const float* __restrict__ beta,
                                            const float* __restrict__ mean,
                                            const float* __restrict__ var) {
    int plane = blockIdx.x;
    int c = plane & (MIDC-1);
    __shared__ float tile[66*66];
    const float* src = g_buf1 + (size_t)plane*HW;
    for (int idx = threadIdx.x; idx < 66*66; idx += 256) {
        int r = idx / 66, cc = idx - r*66;
        int y = r - 1, x = cc - 1;
        float v = 0.f;
        if ((unsigned)y < 64u && (unsigned)x < 64u) v = src[y*64 + x];
        tile[idx] = v;
    }
    __syncthreads();
    float w0 = dww[c*9+0], w1 = dww[c*9+1], w2 = dww[c*9+2];
    float w3 = dww[c*9+3], w4 = dww[c*9+4], w5 = dww[c*9+5];
    float w6 = dww[c*9+6], w7 = dww[c*9+7], w8 = dww[c*9+8];
    float scale = gamma[c] * rsqrtf(var[c] + 1e-5f);
    float shift = beta[c] - mean[c]*scale;
    float bia = dwb[c];
    float s = 0.f, sq = 0.f;
    float* dst = g_xr + (size_t)plane*HW;
#pragma unroll
    for (int i = 0; i < 16; i++) {
        int p = threadIdx.x + i*256;
        int py = p >> 6, px = p & 63;
        const float* t0 = &tile[py*66 + px];
        float acc = t0[0]*w0 + t0[1]*w1 + t0[2]*w2
                  + t0[66]*w3 + t0[67]*w4 + t0[68]*w5
                  + t0[132]*w6 + t0[133]*w7 + t0[134]*w8;
        acc = fmaxf((acc + bia)*scale + shift, 0.f);
        dst[p] = acc;
        s += acc; sq += acc*acc;
    }
#pragma unroll
    for (int o = 16; o; o >>= 1) {
        s  += __shfl_xor_sync(0xffffffffu, s,  o);
        sq += __shfl_xor_sync(0xffffffffu, sq, o);
    }
    __shared__ float rs[8], rq[8];
    int wid = threadIdx.x >> 5;
    if ((threadIdx.x & 31) == 0) { rs[wid] = s; rq[wid] = sq; }
    __syncthreads();
    if (threadIdx.x == 0) {
        float ts = 0.f, tq = 0.f;
#pragma unroll
        for (int w = 0; w < 8; w++) { ts += rs[w]; tq += rq[w]; }
        g_means[plane] = ts * (1.f/4096.f);
        g_nrm[plane]   = sqrtf(tq);          // Parseval: ||F||2 == ||xr||2 (ortho)
    }
}

// ---------------- K3: SE gate MLP ----------------
__global__ void __launch_bounds__(256) k_gate(const float* __restrict__ w1,
                                              const float* __restrict__ b1,
                                              const float* __restrict__ w2,
                                              const float* __restrict__ b2) {
    int b = blockIdx.x;
    __shared__ float sm[MIDC];
    __shared__ float sh[32];
    int tid = threadIdx.x;
    sm[tid] = g_means[b*MIDC + tid];
    __syncthreads();
    if (tid < 32) {
        float a = b1[tid];
        const float* wr = w1 + tid*MIDC;
        for (int c2 = 0; c2 < MIDC; c2++) a += wr[c2]*sm[c2];
        sh[tid] = fmaxf(a, 0.f);
    }
    __syncthreads();
    float a = b2[tid];
    const float* wr = w2 + tid*32;
#pragma unroll
    for (int j = 0; j < 32; j++) a += wr[j]*sh[j];
    g_gate[b*MIDC + tid] = 1.f / (1.f + expf(-a));
}

// ---------------- K4: forward FFT (ortho) -> Fr,Fi (bitrev order) ----------------
__global__ void __launch_bounds__(256) k_fft_fwd() {
    __shared__ float Ar[64*65], Ai[64*65], twr[32], twi[32];
    int plane = blockIdx.x, tid = threadIdx.x;
    const float* src = g_xr + (size_t)plane*HW;
#pragma unroll
    for (int i = 0; i < 16; i++) {
        int p = tid + i*256; int r = p >> 6, c = p & 63;
        Ar[r*65+c] = src[p]; Ai[r*65+c] = 0.f;
    }
    fft_load_tw(twr, twi, tid);
    __syncthreads();
    fft_dif(Ar, Ai, twr, twi, tid, false);
    fft_dif(Ar, Ai, twr, twi, tid, true);
    float* fr = g_Fr + (size_t)plane*HW;
    float* fi = g_Fi + (size_t)plane*HW;
#pragma unroll
    for (int i = 0; i < 16; i++) {
        int p = tid + i*256; int r = p >> 6, c = p & 63;
        fr[p] = Ar[r*65+c] * (1.f/64.f);
        fi[p] = Ai[r*65+c] * (1.f/64.f);
    }
}

// ---------------- K5: FFT channel attention ----------------
__global__ void __launch_bounds__(256) k_attn(const float* __restrict__ temp) {
    int h = blockIdx.x, b = blockIdx.y;
    size_t base = ((size_t)b*MIDC + h*32) * HW;
    __shared__ float sFr[32][65], sFi[32][65];
    __shared__ float sM[32][33], sA[32][33], sN[32];
    int tid = threadIdx.x;
    int c0 = (tid >> 4) * 2, d0 = (tid & 15) * 2;
    float a00 = 0.f, a01 = 0.f, a10 = 0.f, a11 = 0.f;
    for (int n0 = 0; n0 < HW; n0 += 64) {
        __syncthreads();
        for (int idx = tid; idx < 32*64; idx += 256) {
            int cc = idx >> 6, nn = idx & 63;
            sFr[cc][nn] = g_Fr[base + (size_t)cc*HW + n0 + nn];
            sFi[cc][nn] = g_Fi[base + (size_t)cc*HW + n0 + nn];
        }
        __syncthreads();
#pragma unroll 4
        for (int nn = 0; nn < 64; nn++) {
            float rc0 = sFr[c0][nn],   rc1 = sFr[c0+1][nn];
            float rd0 = sFr[d0][nn],   rd1 = sFr[d0+1][nn];
            float ic0 = sFi[c0][nn],   ic1 = sFi[c0+1][nn];
            float id0 = sFi[d0][nn],   id1 = sFi[d0+1][nn];
            a00 += rc0*rd0 - ic0*id0;
            a01 += rc0*rd1 - ic0*id1;
            a10 += rc1*rd0 - ic1*id0;
            a11 += rc1*rd1 - ic1*id1;
        }
    }
    if (tid < 32) sN[tid] = fmaxf(g_nrm[b*MIDC + h*32 + tid], 1e-12f);
    __syncthreads();
    float tK = temp[h];
    sM[c0  ][d0  ] = a00 * tK / (sN[c0  ]*sN[d0  ]);
    sM[c0  ][d0+1] = a01 * tK / (sN[c0  ]*sN[d0+1]);
    sM[c0+1][d0  ] = a10 * tK / (sN[c0+1]*sN[d0  ]);
    sM[c0+1][d0+1] = a11 * tK / (sN[c0+1]*sN[d0+1]);
    __syncthreads();
    int lane = tid & 31;
#pragma unroll
    for (int rr = 0; rr < 4; rr++) {
        int row = (tid >> 5)*4 + rr;
        float v = sM[row][lane];
        float mx = v;
#pragma unroll
        for (int o = 16; o; o >>= 1) mx = fmaxf(mx, __shfl_xor_sync(0xffffffffu, mx, o));
        float e = expf(v - mx);
        float sm = e;
#pragma unroll
        for (int o = 16; o; o >>= 1) sm += __shfl_xor_sync(0xffffffffu, sm, o);
        sA[row][lane] = e / sm;
    }
    // out[c,n] = sum_d attn[c,d] * Fr[d,n]
    for (int n0 = 0; n0 < HW; n0 += 64) {
        __syncthreads();
        for (int idx = tid; idx < 32*64; idx += 256) {
            int cc = idx >> 6, nn = idx & 63;
            sFr[cc][nn] = g_Fr[base + (size_t)cc*HW + n0 + nn];
        }
        __syncthreads();
#pragma unroll
        for (int i = 0; i < 8; i++) {
            int idx = tid + i*256;
            int cc = idx >> 6, nn = idx & 63;
            float acc = 0.f;
#pragma unroll
            for (int d = 0; d < 32; d++) acc += sA[cc][d] * sFr[d][nn];
            g_buf1[base + (size_t)cc*HW + n0 + nn] = acc;
        }
    }
}

// ---------------- K6: inverse FFT (ortho) of attn branch -> fused_bf[:, 0:256] ----------------
__global__ void __launch_bounds__(256) k_ifft_attn() {
    __shared__ float Ar[64*65], Ai[64*65], twr[32], twi[32];
    int plane = blockIdx.x, tid = threadIdx.x;
    int b = plane >> 8, c = plane & (MIDC-1);
    const float* src = g_buf1 + (size_t)plane*HW;
#pragma unroll
    for (int i = 0; i < 16; i++) {
        int p = tid + i*256; int r = p >> 6, cc = p & 63;
        Ar[r*65+cc] = src[p]; Ai[r*65+cc] = 0.f;
    }
    fft_load_tw(twr, twi, tid);
    __syncthreads();
    fft_dit(Ar, Ai, twr, twi, tid, false);
    fft_dit(Ar, Ai, twr, twi, tid, true);
    __nv_bfloat16* dst = g_fused_bf + ((size_t)b*INDIM + c)*HW;
#pragma unroll
    for (int i = 0; i < 16; i++) {
        int p = tid + i*256; int r = p >> 6, cc = p & 63;
        dst[p] = __float2bfloat16(Ar[r*65+cc] * (1.f/64.f));   // ortho ifft2
    }
}

// ---------------- K7: fwm -> fused_bf[:, 256:512] ----------------
__global__ void __launch_bounds__(256) k_fwm() {
    __shared__ float Ar[64*65], Ai[64*65], twr[32], twi[32];
    int plane = blockIdx.x, tid = threadIdx.x;
    int b = plane >> 8, c = plane & (MIDC-1);
    float gv = g_gate[b*MIDC + c];
    const float* src = g_xr + (size_t)plane*HW;
#pragma unroll
    for (int i = 0; i < 16; i++) {
        int p = tid + i*256; int r = p >> 6, cc = p & 63;
        Ar[r*65+cc] = gv * src[p]; Ai[r*65+cc] = 0.f;
    }
    fft_load_tw(twr, twi, tid);
    __syncthreads();
    fft_dif(Ar, Ai, twr, twi, tid, false);   // forward, unscaled (default fft2 norm)
    fft_dif(Ar, Ai, twr, twi, tid, true);
    const float* fr = g_Fr + (size_t)plane*HW;
    const float* fi = g_Fi + (size_t)plane*HW;
#pragma unroll
    for (int i = 0; i < 16; i++) {
        int p = tid + i*256; int r = p >> 6, cc = p & 63;
        int a = r*65 + cc;
        float xr_ = Ar[a], xi_ = Ai[a];
        float yr = fr[p], yi = fi[p];
        Ar[a] = xr_*yr - xi_*yi;
        Ai[a] = xr_*yi + xi_*yr;
    }
    __syncthreads();
    fft_dit(Ar, Ai, twr, twi, tid, false);
    fft_dit(Ar, Ai, twr, twi, tid, true);
    __nv_bfloat16* dst = g_fused_bf + ((size_t)b*INDIM + MIDC + c)*HW;
#pragma unroll
    for (int i = 0; i < 16; i++) {
        int p = tid + i*256; int r = p >> 6, cc = p & 63;
        dst[p] = __float2bfloat16(Ar[r*65+cc] * (1.f/4096.f)); // default ifft2 norm
    }
}

// ---------------- launch ----------------
extern "C" void kernel_launch(void* const* d_in, const int* in_sizes, int n_in,
                              void* d_out, int out_size) {
    (void)in_sizes; (void)n_in; (void)out_size;
    const float* x        = (const float*)d_in[0];
    const float* reduce_w = (const float*)d_in[1];
    const float* reduce_b = (const float*)d_in[2];
    const float* dw_w     = (const float*)d_in[3];
    const float* dw_b     = (const float*)d_in[4];
    const float* bn_gamma = (const float*)d_in[5];
    const float* bn_beta  = (const float*)d_in[6];
    const float* bn_mean  = (const float*)d_in[7];
    const float* bn_var   = (const float*)d_in[8];
    const float* gate_w1  = (const float*)d_in[9];
    const float* gate_b1  = (const float*)d_in[10];
    const float* gate_w2  = (const float*)d_in[11];
    const float* gate_b2  = (const float*)d_in[12];
    const float* temp     = (const float*)d_in[13];
    const float* post_w   = (const float*)d_in[14];
    const float* post_b   = (const float*)d_in[15];
    float* out = (float*)d_out;

    static int smem_set = 0;
    if (!smem_set) {
        cudaFuncSetAttribute(k_wmma_gemm, cudaFuncAttributeMaxDynamicSharedMemorySize,
                             GEMM_SMEM);
        smem_set = 1;
    }

    __nv_bfloat16 *p_xbf, *p_fbf, *p_wred, *p_wpost;
    cudaGetSymbolAddress((void**)&p_xbf,   g_x_bf);
    cudaGetSymbolAddress((void**)&p_fbf,   g_fused_bf);
    cudaGetSymbolAddress((void**)&p_wred,  g_wred);
    cudaGetSymbolAddress((void**)&p_wpost, g_wpost);
    float* p_buf1;
    cudaGetSymbolAddress((void**)&p_buf1, g_buf1);

    // conversions
    k_cvt<<<(BATCH*INDIM*HW/4 + 255)/256, 256>>>(x, p_xbf, BATCH*INDIM*HW);
    k_cvt<<<(MIDC*INDIM/4 + 255)/256, 256>>>(reduce_w, p_wred, MIDC*INDIM);
    k_cvt<<<(INDIM*2*MIDC/4 + 255)/256, 256>>>(post_w, p_wpost, INDIM*2*MIDC);

    // reduce GEMM: [256,4096] = W[256,512] * x[512,4096] + reduce_b, per batch
    k_wmma_gemm<<<dim3(32, 2, BATCH), 256, GEMM_SMEM>>>(
        p_wred, p_xbf, reduce_b, nullptr, p_buf1, MIDC);

    k_dw<<<BATCH*MIDC, 256>>>(dw_w, dw_b, bn_gamma, bn_beta, bn_mean, bn_var);
    k_gate<<<BATCH, 256>>>(gate_w1, gate_b1, gate_w2, gate_b2);
    k_fft_fwd<<<BATCH*MIDC, 256>>>();
    k_attn<<<dim3(HEADS, BATCH), 256>>>(temp);
    k_ifft_attn<<<BATCH*MIDC, 256>>>();
    k_fwm<<<BATCH*MIDC, 256>>>();

    // post GEMM: [512,4096] = W[512,512] * fused[512,4096] + post_b + x
    k_wmma_gemm<<<dim3(32, 4, BATCH), 256, GEMM_SMEM>>>(
        p_wpost, p_fbf, post_b, x, out, INDIM);
}

// round 4
// speedup vs baseline: 2.0145x; 1.2850x over previous
#include <cuda_runtime.h>
#include <cuda_bf16.h>
#include <mma.h>
#include <math.h>
#include <stdint.h>

using namespace nvcuda;

#define BATCH 16
#define INDIM 512
#define MIDC  256
#define HW    4096
#define HEADS 8

// ---------------- scratch (device globals; no allocation) ----------------
__device__ float g_buf1[BATCH*MIDC*HW];   // xr0 (pre-dw), later attn frequency output
__device__ float g_xr  [BATCH*MIDC*HW];   // post dw+BN+ReLU
__device__ float g_Fr  [BATCH*MIDC*HW];   // fft_feat real (ortho, digit-rev order)
__device__ float g_Fi  [BATCH*MIDC*HW];   // fft_feat imag
__device__ float g_means[BATCH*MIDC];
__device__ float g_nrm  [BATCH*MIDC];
__device__ float g_gate [BATCH*MIDC];
// bf16 operands for tensor-core GEMMs
__device__ __nv_bfloat16 g_x_bf    [BATCH*INDIM*HW];  // x in bf16
__device__ __nv_bfloat16 g_fused_bf[BATCH*INDIM*HW];  // [attn_out | fwm] bf16
__device__ __nv_bfloat16 g_wred    [MIDC*INDIM];
__device__ __nv_bfloat16 g_wpost   [INDIM*2*MIDC];

// ================= wmma bf16 GEMM (unchanged from R3) =================
#define AS_STRIDE 40
#define BS_STRIDE 136
#define CS_STRIDE 132
#define GEMM_SMEM (128*CS_STRIDE*4)

__global__ void __launch_bounds__(256)
k_wmma_gemm(const __nv_bfloat16* __restrict__ W,
            const __nv_bfloat16* __restrict__ act,
            const float* __restrict__ bias,
            const float* __restrict__ resid,
            float* __restrict__ out,
            int Mtot) {
    extern __shared__ char sm[];
    __nv_bfloat16* As = (__nv_bfloat16*)sm;
    __nv_bfloat16* Bs = (__nv_bfloat16*)(sm + 128*AS_STRIDE*2);
    float*         Cs = (float*)sm;

    int tid = threadIdx.x;
    int w   = tid >> 5;
    int wm  = w & 3;
    int wn  = w >> 2;
    int nb = blockIdx.x * 128, mb = blockIdx.y * 128, b = blockIdx.z;

    const __nv_bfloat16* Ag = W + (size_t)mb * 512;
    const __nv_bfloat16* Bg = act + (size_t)b * 512 * 4096 + nb;

    wmma::fragment<wmma::accumulator, 16, 16, 16, float> acc[2][4];
#pragma unroll
    for (int i = 0; i < 2; i++)
#pragma unroll
        for (int j = 0; j < 4; j++) wmma::fill_fragment(acc[i][j], 0.0f);

    for (int kc = 0; kc < 512; kc += 32) {
        __syncthreads();
#pragma unroll
        for (int t = 0; t < 2; t++) {
            int id = tid + t * 256;
            int r = id >> 2, c8 = (id & 3) * 8;
            uint4 v = *(const uint4*)(Ag + (size_t)r * 512 + kc + c8);
            *(uint4*)(As + r * AS_STRIDE + c8) = v;
        }
#pragma unroll
        for (int t = 0; t < 2; t++) {
            int id = tid + t * 256;
            int r = id >> 4, c8 = (id & 15) * 8;
            uint4 v = *(const uint4*)(Bg + (size_t)(kc + r) * 4096 + c8);
            *(uint4*)(Bs + r * BS_STRIDE + c8) = v;
        }
        __syncthreads();
#pragma unroll
        for (int ks = 0; ks < 2; ks++) {
            wmma::fragment<wmma::matrix_a, 16, 16, 16, __nv_bfloat16, wmma::row_major> af[2];
            wmma::fragment<wmma::matrix_b, 16, 16, 16, __nv_bfloat16, wmma::row_major> bf[4];
#pragma unroll
            for (int i = 0; i < 2; i++)
                wmma::load_matrix_sync(af[i], As + (wm*32 + i*16) * AS_STRIDE + ks*16, AS_STRIDE);
#pragma unroll
            for (int j = 0; j < 4; j++)
                wmma::load_matrix_sync(bf[j], Bs + (ks*16) * BS_STRIDE + wn*64 + j*16, BS_STRIDE);
#pragma unroll
            for (int i = 0; i < 2; i++)
#pragma unroll
                for (int j = 0; j < 4; j++)
                    wmma::mma_sync(acc[i][j], af[i], bf[j], acc[i][j]);
        }
    }
    __syncthreads();
#pragma unroll
    for (int i = 0; i < 2; i++)
#pragma unroll
        for (int j = 0; j < 4; j++)
            wmma::store_matrix_sync(Cs + (wm*32 + i*16) * CS_STRIDE + wn*64 + j*16,
                                    acc[i][j], CS_STRIDE, wmma::mem_row_major);
    __syncthreads();
#pragma unroll
    for (int t = 0; t < 16; t++) {
        int id = tid + t * 256;
        int r = id >> 5, c = (id & 31) * 4;
        float bi = bias ? bias[mb + r] : 0.0f;
        float4 v = *(float4*)(Cs + r * CS_STRIDE + c);
        v.x += bi; v.y += bi; v.z += bi; v.w += bi;
        size_t off = ((size_t)b * Mtot + mb + r) * 4096 + nb + c;
        if (resid) {
            float4 rr = *(const float4*)(resid + off);
            v.x += rr.x; v.y += rr.y; v.z += rr.z; v.w += rr.w;
        }
        *(float4*)(out + off) = v;
    }
}

// ---------------- conversion ----------------
__global__ void __launch_bounds__(256) k_cvt(const float* __restrict__ src,
                                             __nv_bfloat16* __restrict__ dst, int n) {
    int i = (blockIdx.x * 256 + threadIdx.x) * 4;
    if (i < n) {
        float4 v = *(const float4*)(src + i);
        __nv_bfloat162 p0 = __floats2bfloat162_rn(v.x, v.y);
        __nv_bfloat162 p1 = __floats2bfloat162_rn(v.z, v.w);
        uint2 pk;
        pk.x = *(uint32_t*)&p0; pk.y = *(uint32_t*)&p1;
        *(uint2*)(dst + i) = pk;
    }
}

// ================= radix-4 FFT (64-pt, 3 stages, in-place smem) =================
// Forward: DIF, natural -> digit-reversed.  Inverse: DIT, digit-reversed -> natural
// (unscaled IDFT).  tw[k] = e^{-2*pi*i*k/64}.

template<int Q, int M>
__device__ __forceinline__ void fft4s_fwd(float* Ar, float* Ai,
                                          const float* twr, const float* twi,
                                          int tid, bool col) {
#pragma unroll
    for (int i = 0; i < 4; i++) {
        int t = tid + (i << 8);
        int line = t >> 4;
        int j16 = t & 15;
        int blk = j16 / Q, j = j16 - blk * Q;
        int base = blk * (4 * Q) + j;
        int p0 = base, p1 = base + Q, p2 = base + 2*Q, p3 = base + 3*Q;
        int a0 = col ? p0*65 + line : line*65 + p0;
        int a1 = col ? p1*65 + line : line*65 + p1;
        int a2 = col ? p2*65 + line : line*65 + p2;
        int a3 = col ? p3*65 + line : line*65 + p3;
        float x0r=Ar[a0], x0i=Ai[a0], x1r=Ar[a1], x1i=Ai[a1];
        float x2r=Ar[a2], x2i=Ai[a2], x3r=Ar[a3], x3i=Ai[a3];
        float t0r=x0r+x2r, t0i=x0i+x2i;
        float t1r=x0r-x2r, t1i=x0i-x2i;
        float t2r=x1r+x3r, t2i=x1i+x3i;
        float t3r=x1i-x3i, t3i=x3r-x1r;          // -i*(x1-x3)
        Ar[a0]=t0r+t2r; Ai[a0]=t0i+t2i;
        float w1r=twr[M*j],   w1i=twi[M*j];
        float w2r=twr[2*M*j], w2i=twi[2*M*j];
        float w3r=twr[3*M*j], w3i=twi[3*M*j];
        float u1r=t1r+t3r, u1i=t1i+t3i;
        Ar[a1]=u1r*w1r-u1i*w1i; Ai[a1]=u1r*w1i+u1i*w1r;
        float u2r=t0r-t2r, u2i=t0i-t2i;
        Ar[a2]=u2r*w2r-u2i*w2i; Ai[a2]=u2r*w2i+u2i*w2r;
        float u3r=t1r-t3r, u3i=t1i-t3i;
        Ar[a3]=u3r*w3r-u3i*w3i; Ai[a3]=u3r*w3i+u3i*w3r;
    }
}

template<int Q, int M>
__device__ __forceinline__ void fft4s_inv(float* Ar, float* Ai,
                                          const float* twr, const float* twi,
                                          int tid, bool col) {
#pragma unroll
    for (int i = 0; i < 4; i++) {
        int t = tid + (i << 8);
        int line = t >> 4;
        int j16 = t & 15;
        int blk = j16 / Q, j = j16 - blk * Q;
        int base = blk * (4 * Q) + j;
        int p0 = base, p1 = base + Q, p2 = base + 2*Q, p3 = base + 3*Q;
        int a0 = col ? p0*65 + line : line*65 + p0;
        int a1 = col ? p1*65 + line : line*65 + p1;
        int a2 = col ? p2*65 + line : line*65 + p2;
        int a3 = col ? p3*65 + line : line*65 + p3;
        float u0r=Ar[a0], u0i=Ai[a0];
        float v1r=Ar[a1], v1i=Ai[a1];
        float v2r=Ar[a2], v2i=Ai[a2];
        float v3r=Ar[a3], v3i=Ai[a3];
        // untwiddle with conj(W)
        float w1r=twr[M*j],   w1i=twi[M*j];
        float w2r=twr[2*M*j], w2i=twi[2*M*j];
        float w3r=twr[3*M*j], w3i=twi[3*M*j];
        float b1r=v1r*w1r+v1i*w1i, b1i=v1i*w1r-v1r*w1i;
        float b2r=v2r*w2r+v2i*w2i, b2i=v2i*w2r-v2r*w2i;
        float b3r=v3r*w3r+v3i*w3i, b3i=v3i*w3r-v3r*w3i;
        float s0r=u0r+b2r, s0i=u0i+b2i;
        float s1r=u0r-b2r, s1i=u0i-b2i;
        float s2r=b1r+b3r, s2i=b1i+b3i;
        float s3r=b3i-b1i, s3i=b1r-b3r;          // +i*(b1-b3)
        Ar[a0]=s0r+s2r; Ai[a0]=s0i+s2i;
        Ar[a1]=s1r+s3r; Ai[a1]=s1i+s3i;
        Ar[a2]=s0r-s2r; Ai[a2]=s0i-s2i;
        Ar[a3]=s1r-s3r; Ai[a3]=s1i-s3i;
    }
}

__device__ __forceinline__ void fft4_fwd_dim(float* Ar, float* Ai,
                                             const float* twr, const float* twi,
                                             int tid, bool col) {
    fft4s_fwd<16,1>(Ar, Ai, twr, twi, tid, col); __syncthreads();
    fft4s_fwd<4,4> (Ar, Ai, twr, twi, tid, col); __syncthreads();
    fft4s_fwd<1,16>(Ar, Ai, twr, twi, tid, col); __syncthreads();
}

__device__ __forceinline__ void fft4_inv_dim(float* Ar, float* Ai,
                                             const float* twr, const float* twi,
                                             int tid, bool col) {
    fft4s_inv<1,16>(Ar, Ai, twr, twi, tid, col); __syncthreads();
    fft4s_inv<4,4> (Ar, Ai, twr, twi, tid, col); __syncthreads();
    fft4s_inv<16,1>(Ar, Ai, twr, twi, tid, col); __syncthreads();
}

__device__ __forceinline__ void fft_load_tw64(float* twr, float* twi, int tid) {
    if (tid < 64) {
        float s, c;
        sincosf(-6.28318530717958647692f * (float)tid * (1.0f/64.0f), &s, &c);
        twr[tid] = c; twi[tid] = s;
    }
}

// ---------------- K2: depthwise 3x3 + bias + BN + ReLU + stats ----------------
__global__ void __launch_bounds__(256) k_dw(const float* __restrict__ dww,
                                            const float* __restrict__ dwb,
                                            const float* __restrict__ gamma,
                                            const float* __restrict__ beta,
                                            const float* __restrict__ mean,
                                            const float* __restrict__ var) {
    int plane = blockIdx.x;
    int c = plane & (MIDC-1);
    __shared__ float tile[66*66];
    const float* src = g_buf1 + (size_t)plane*HW;
    for (int idx = threadIdx.x; idx < 66*66; idx += 256) {
        int r = idx / 66, cc = idx - r*66;
        int y = r - 1, x = cc - 1;
        float v = 0.f;
        if ((unsigned)y < 64u && (unsigned)x < 64u) v = src[y*64 + x];
        tile[idx] = v;
    }
    __syncthreads();
    float w0 = dww[c*9+0], w1 = dww[c*9+1], w2 = dww[c*9+2];
    float w3 = dww[c*9+3], w4 = dww[c*9+4], w5 = dww[c*9+5];
    float w6 = dww[c*9+6], w7 = dww[c*9+7], w8 = dww[c*9+8];
    float scale = gamma[c] * rsqrtf(var[c] + 1e-5f);
    float shift = beta[c] - mean[c]*scale;
    float bia = dwb[c];
    float s = 0.f, sq = 0.f;
    float* dst = g_xr + (size_t)plane*HW;
#pragma unroll
    for (int i = 0; i < 16; i++) {
        int p = threadIdx.x + i*256;
        int py = p >> 6, px = p & 63;
        const float* t0 = &tile[py*66 + px];
        float acc = t0[0]*w0 + t0[1]*w1 + t0[2]*w2
                  + t0[66]*w3 + t0[67]*w4 + t0[68]*w5
                  + t0[132]*w6 + t0[133]*w7 + t0[134]*w8;
        acc = fmaxf((acc + bia)*scale + shift, 0.f);
        dst[p] = acc;
        s += acc; sq += acc*acc;
    }
#pragma unroll
    for (int o = 16; o; o >>= 1) {
        s  += __shfl_xor_sync(0xffffffffu, s,  o);
        sq += __shfl_xor_sync(0xffffffffu, sq, o);
    }
    __shared__ float rs[8], rq[8];
    int wid = threadIdx.x >> 5;
    if ((threadIdx.x & 31) == 0) { rs[wid] = s; rq[wid] = sq; }
    __syncthreads();
    if (threadIdx.x == 0) {
        float ts = 0.f, tq = 0.f;
#pragma unroll
        for (int w = 0; w < 8; w++) { ts += rs[w]; tq += rq[w]; }
        g_means[plane] = ts * (1.f/4096.f);
        g_nrm[plane]   = sqrtf(tq);          // Parseval: ||F||2 == ||xr||2 (ortho)
    }
}

// ---------------- K3: SE gate MLP ----------------
__global__ void __launch_bounds__(256) k_gate(const float* __restrict__ w1,
                                              const float* __restrict__ b1,
                                              const float* __restrict__ w2,
                                              const float* __restrict__ b2) {
    int b = blockIdx.x;
    __shared__ float sm[MIDC];
    __shared__ float sh[32];
    int tid = threadIdx.x;
    sm[tid] = g_means[b*MIDC + tid];
    __syncthreads();
    if (tid < 32) {
        float a = b1[tid];
        const float* wr = w1 + tid*MIDC;
        for (int c2 = 0; c2 < MIDC; c2++) a += wr[c2]*sm[c2];
        sh[tid] = fmaxf(a, 0.f);
    }
    __syncthreads();
    float a = b2[tid];
    const float* wr = w2 + tid*32;
#pragma unroll
    for (int j = 0; j < 32; j++) a += wr[j]*sh[j];
    g_gate[b*MIDC + tid] = 1.f / (1.f + expf(-a));
}

// ---------------- K4: forward FFT (ortho) -> Fr,Fi (digit-rev order) ----------------
__global__ void __launch_bounds__(256) k_fft_fwd() {
    __shared__ float Ar[64*65], Ai[64*65], twr[64], twi[64];
    int plane = blockIdx.x, tid = threadIdx.x;
    const float* src = g_xr + (size_t)plane*HW;
#pragma unroll
    for (int i = 0; i < 16; i++) {
        int p = tid + i*256; int r = p >> 6, c = p & 63;
        Ar[r*65+c] = src[p]; Ai[r*65+c] = 0.f;
    }
    fft_load_tw64(twr, twi, tid);
    __syncthreads();
    fft4_fwd_dim(Ar, Ai, twr, twi, tid, false);
    fft4_fwd_dim(Ar, Ai, twr, twi, tid, true);
    float* fr = g_Fr + (size_t)plane*HW;
    float* fi = g_Fi + (size_t)plane*HW;
#pragma unroll
    for (int i = 0; i < 16; i++) {
        int p = tid + i*256; int r = p >> 6, c = p & 63;
        fr[p] = Ar[r*65+c] * (1.f/64.f);
        fi[p] = Ai[r*65+c] * (1.f/64.f);
    }
}

// ---------------- K5: FFT channel attention (register-blocked) ----------------
__global__ void __launch_bounds__(256) k_attn(const float* __restrict__ temp) {
    int h = blockIdx.x, b = blockIdx.y;
    size_t base = ((size_t)b*MIDC + h*32) * HW;
    __shared__ float sFr[32][65], sFi[32][65];
    __shared__ float sRed[4][1024];
    __shared__ float sA[32][33], sN[32];
    int tid = threadIdx.x;
    int nsub = tid >> 6;
    int tt = tid & 63;
    int c0 = (tt >> 3) * 4, d0 = (tt & 7) * 4;
    float acc[4][4] = {};
    // phase 1: Gram (real part of complex Gram without conjugate)
    for (int n0 = 0; n0 < HW; n0 += 64) {
        __syncthreads();
        for (int idx = tid; idx < 2048; idx += 256) {
            int cc = idx >> 6, nn = idx & 63;
            sFr[cc][nn] = g_Fr[base + (size_t)cc*HW + n0 + nn];
            sFi[cc][nn] = g_Fi[base + (size_t)cc*HW + n0 + nn];
        }
        __syncthreads();
        int nlo = nsub * 16;
#pragma unroll 4
        for (int nn = nlo; nn < nlo + 16; nn++) {
            float rc[4], ic[4], rd[4], jd[4];
#pragma unroll
            for (int i = 0; i < 4; i++) { rc[i] = sFr[c0+i][nn]; ic[i] = sFi[c0+i][nn]; }
#pragma unroll
            for (int j = 0; j < 4; j++) { rd[j] = sFr[d0+j][nn]; jd[j] = sFi[d0+j][nn]; }
#pragma unroll
            for (int i = 0; i < 4; i++)
#pragma unroll
                for (int j = 0; j < 4; j++)
                    acc[i][j] += rc[i]*rd[j] - ic[i]*jd[j];
        }
    }
#pragma unroll
    for (int i = 0; i < 4; i++)
#pragma unroll
        for (int j = 0; j < 4; j++)
            sRed[nsub][tt*16 + i*4 + j] = acc[i][j];
    if (tid < 32) sN[tid] = fmaxf(g_nrm[b*MIDC + h*32 + tid], 1e-12f);
    __syncthreads();
    // finalize logits: normalize + temperature
    float tK = temp[h];
#pragma unroll
    for (int q = 0; q < 4; q++) {
        int e = tid*4 + q;
        int te = e >> 4, sub = e & 15;
        int i = sub >> 2, j = sub & 3;
        int c = (te >> 3)*4 + i, d = (te & 7)*4 + j;
        float v = sRed[0][e] + sRed[1][e] + sRed[2][e] + sRed[3][e];
        sA[c][d] = v * tK / (sN[c] * sN[d]);
    }
    __syncthreads();
    // softmax rows (8 warps x 4 rows)
    int lane = tid & 31;
#pragma unroll
    for (int rr = 0; rr < 4; rr++) {
        int row = (tid >> 5)*4 + rr;
        float v = sA[row][lane];
        float mx = v;
#pragma unroll
        for (int o = 16; o; o >>= 1) mx = fmaxf(mx, __shfl_xor_sync(0xffffffffu, mx, o));
        float e = expf(v - mx);
        float smv = e;
#pragma unroll
        for (int o = 16; o; o >>= 1) smv += __shfl_xor_sync(0xffffffffu, smv, o);
        sA[row][lane] = e / smv;
    }
    // phase 2: out[c,n] = sum_d attn[c,d] * Fr[d,n]  (2c x 4n tiles)
    int cm = (tid >> 4) * 2;
    int nm = (tid & 15) * 4;
    for (int n0 = 0; n0 < HW; n0 += 64) {
        __syncthreads();
        for (int idx = tid; idx < 2048; idx += 256) {
            int cc = idx >> 6, nn = idx & 63;
            sFr[cc][nn] = g_Fr[base + (size_t)cc*HW + n0 + nn];
        }
        __syncthreads();
        float o0[4] = {}, o1[4] = {};
#pragma unroll
        for (int d = 0; d < 32; d++) {
            float a0 = sA[cm][d], a1 = sA[cm+1][d];
            float f0 = sFr[d][nm], f1 = sFr[d][nm+1], f2 = sFr[d][nm+2], f3 = sFr[d][nm+3];
            o0[0] += a0*f0; o0[1] += a0*f1; o0[2] += a0*f2; o0[3] += a0*f3;
            o1[0] += a1*f0; o1[1] += a1*f1; o1[2] += a1*f2; o1[3] += a1*f3;
        }
        *(float4*)&g_buf1[base + (size_t)cm*HW + n0 + nm]     = make_float4(o0[0],o0[1],o0[2],o0[3]);
        *(float4*)&g_buf1[base + (size_t)(cm+1)*HW + n0 + nm] = make_float4(o1[0],o1[1],o1[2],o1[3]);
    }
}

// ---------------- K6: inverse FFT (ortho) of attn branch -> fused_bf[:, 0:256] ------
__global__ void __launch_bounds__(256) k_ifft_attn() {
    __shared__ float Ar[64*65], Ai[64*65], twr[64], twi[64];
    int plane = blockIdx.x, tid = threadIdx.x;
    int b = plane >> 8, c = plane & (MIDC-1);
    const float* src = g_buf1 + (size_t)plane*HW;
#pragma unroll
    for (int i = 0; i < 16; i++) {
        int p = tid + i*256; int r = p >> 6, cc = p & 63;
        Ar[r*65+cc] = src[p]; Ai[r*65+cc] = 0.f;
    }
    fft_load_tw64(twr, twi, tid);
    __syncthreads();
    fft4_inv_dim(Ar, Ai, twr, twi, tid, false);
    fft4_inv_dim(Ar, Ai, twr, twi, tid, true);
    __nv_bfloat16* dst = g_fused_bf + ((size_t)b*INDIM + c)*HW;
#pragma unroll
    for (int i = 0; i < 16; i++) {
        int p = tid + i*256; int r = p >> 6, cc = p & 63;
        dst[p] = __float2bfloat16(Ar[r*65+cc] * (1.f/64.f));   // ortho ifft2
    }
}

// ---------------- K7: fwm = (g/64) * IDFT(F^2) -> fused_bf[:, 256:512] ----------------
// Uses linearity: fft2(g*xr) = g*64*F  =>  fwm = ifft2_default(F * g*64*F) = (g/64)*IDFT(F∘F)
__global__ void __launch_bounds__(256) k_fwm() {
    __shared__ float Ar[64*65], Ai[64*65], twr[64], twi[64];
    int plane = blockIdx.x, tid = threadIdx.x;
    int b = plane >> 8, c = plane & (MIDC-1);
    const float* fr = g_Fr + (size_t)plane*HW;
    const float* fi = g_Fi + (size_t)plane*HW;
#pragma unroll
    for (int i = 0; i < 16; i++) {
        int p = tid + i*256; int r = p >> 6, cc = p & 63;
        float xr_ = fr[p], xi_ = fi[p];
        Ar[r*65+cc] = xr_*xr_ - xi_*xi_;       // complex square
        Ai[r*65+cc] = 2.f * xr_ * xi_;
    }
    fft_load_tw64(twr, twi, tid);
    __syncthreads();
    fft4_inv_dim(Ar, Ai, twr, twi, tid, false);
    fft4_inv_dim(Ar, Ai, twr, twi, tid, true);
    float sc = g_gate[b*MIDC + c] * (1.f/64.f);
    __nv_bfloat16* dst = g_fused_bf + ((size_t)b*INDIM + MIDC + c)*HW;
#pragma unroll
    for (int i = 0; i < 16; i++) {
        int p = tid + i*256; int r = p >> 6, cc = p & 63;
        dst[p] = __float2bfloat16(Ar[r*65+cc] * sc);
    }
}

// ---------------- launch ----------------
extern "C" void kernel_launch(void* const* d_in, const int* in_sizes, int n_in,
                              void* d_out, int out_size) {
    (void)in_sizes; (void)n_in; (void)out_size;
    const float* x        = (const float*)d_in[0];
    const float* reduce_w = (const float*)d_in[1];
    const float* reduce_b = (const float*)d_in[2];
    const float* dw_w     = (const float*)d_in[3];
    const float* dw_b     = (const float*)d_in[4];
    const float* bn_gamma = (const float*)d_in[5];
    const float* bn_beta  = (const float*)d_in[6];
    const float* bn_mean  = (const float*)d_in[7];
    const float* bn_var   = (const float*)d_in[8];
    const float* gate_w1  = (const float*)d_in[9];
    const float* gate_b1  = (const float*)d_in[10];
    const float* gate_w2  = (const float*)d_in[11];
    const float* gate_b2  = (const float*)d_in[12];
    const float* temp     = (const float*)d_in[13];
    const float* post_w   = (const float*)d_in[14];
    const float* post_b   = (const float*)d_in[15];
    float* out = (float*)d_out;

    cudaFuncSetAttribute(k_wmma_gemm, cudaFuncAttributeMaxDynamicSharedMemorySize,
                         GEMM_SMEM);

    __nv_bfloat16 *p_xbf, *p_fbf, *p_wred, *p_wpost;
    cudaGetSymbolAddress((void**)&p_xbf,   g_x_bf);
    cudaGetSymbolAddress((void**)&p_fbf,   g_fused_bf);
    cudaGetSymbolAddress((void**)&p_wred,  g_wred);
    cudaGetSymbolAddress((void**)&p_wpost, g_wpost);
    float* p_buf1;
    cudaGetSymbolAddress((void**)&p_buf1, g_buf1);

    // conversions
    k_cvt<<<(BATCH*INDIM*HW/4 + 255)/256, 256>>>(x, p_xbf, BATCH*INDIM*HW);
    k_cvt<<<(MIDC*INDIM/4 + 255)/256, 256>>>(reduce_w, p_wred, MIDC*INDIM);
    k_cvt<<<(INDIM*2*MIDC/4 + 255)/256, 256>>>(post_w, p_wpost, INDIM*2*MIDC);

    // reduce GEMM: [256,4096] = W[256,512] * x[512,4096] + reduce_b, per batch
    k_wmma_gemm<<<dim3(32, 2, BATCH), 256, GEMM_SMEM>>>(
        p_wred, p_xbf, reduce_b, nullptr, p_buf1, MIDC);

    k_dw<<<BATCH*MIDC, 256>>>(dw_w, dw_b, bn_gamma, bn_beta, bn_mean, bn_var);
    k_gate<<<BATCH, 256>>>(gate_w1, gate_b1, gate_w2, gate_b2);
    k_fft_fwd<<<BATCH*MIDC, 256>>>();
    k_attn<<<dim3(HEADS, BATCH), 256>>>(temp);
    k_ifft_attn<<<BATCH*MIDC, 256>>>();
    k_fwm<<<BATCH*MIDC, 256>>>();

    // post GEMM: [512,4096] = W[512,512] * fused[512,4096] + post_b + x
    k_wmma_gemm<<<dim3(32, 4, BATCH), 256, GEMM_SMEM>>>(
        p_wpost, p_fbf, post_b, x, out, INDIM);
}

// round 5
// speedup vs baseline: 2.4767x; 1.2294x over previous
#include <cuda_runtime.h>
#include <cuda_bf16.h>
#include <cuda_fp16.h>
#include <mma.h>
#include <math.h>
#include <stdint.h>

using namespace nvcuda;

#define BATCH 16
#define INDIM 512
#define MIDC  256
#define HW    4096
#define HEADS 8

// ---------------- scratch (device globals; no allocation) ----------------
__device__ float  g_buf1[BATCH*MIDC*HW];    // reduce-GEMM output (pre-dw), fp32
__device__ __half g_Fr_h[BATCH*MIDC*HW];    // fft_feat real (ortho, digit-rev), fp16
__device__ __half g_Fi_h[BATCH*MIDC*HW];    // fft_feat imag
__device__ __half g_mix_h[BATCH*MIDC*HW];   // attn frequency output, fp16
__device__ float  g_means[BATCH*MIDC];
__device__ float  g_nrm  [BATCH*MIDC];
__device__ float  g_gate [BATCH*MIDC];
__device__ float  g_gram_part[BATCH*HEADS*8*1024];  // 8 n-slices of partial Grams
__device__ float  g_attnW[BATCH*HEADS*1024];        // softmaxed attention weights
__device__ __nv_bfloat16 g_fused_bf[BATCH*INDIM*HW]; // [attn_out | fwm] bf16
__device__ __nv_bfloat16 g_wred    [MIDC*INDIM];
__device__ __nv_bfloat16 g_wpost   [INDIM*2*MIDC];

// ================= wmma bf16 GEMM (templated act dtype) =================
#define AS_STRIDE 40
#define BS_STRIDE 136
#define CS_STRIDE 132
#define GEMM_SMEM (128*CS_STRIDE*4)

template<bool F32ACT>
__global__ void __launch_bounds__(256)
k_wmma_gemm(const __nv_bfloat16* __restrict__ W,
            const void* __restrict__ actv,
            const float* __restrict__ bias,
            const float* __restrict__ resid,
            float* __restrict__ out,
            int Mtot) {
    extern __shared__ char sm[];
    __nv_bfloat16* As = (__nv_bfloat16*)sm;
    __nv_bfloat16* Bs = (__nv_bfloat16*)(sm + 128*AS_STRIDE*2);
    float*         Cs = (float*)sm;

    int tid = threadIdx.x;
    int w   = tid >> 5;
    int wm  = w & 3;
    int wn  = w >> 2;
    int nb = blockIdx.x * 128, mb = blockIdx.y * 128, b = blockIdx.z;

    const __nv_bfloat16* Ag = W + (size_t)mb * 512;
    const float*         Bg32 = (const float*)actv + (size_t)b * 512 * 4096 + nb;
    const __nv_bfloat16* Bg16 = (const __nv_bfloat16*)actv + (size_t)b * 512 * 4096 + nb;

    wmma::fragment<wmma::accumulator, 16, 16, 16, float> acc[2][4];
#pragma unroll
    for (int i = 0; i < 2; i++)
#pragma unroll
        for (int j = 0; j < 4; j++) wmma::fill_fragment(acc[i][j], 0.0f);

    for (int kc = 0; kc < 512; kc += 32) {
        __syncthreads();
#pragma unroll
        for (int t = 0; t < 2; t++) {
            int id = tid + t * 256;
            int r = id >> 2, c8 = (id & 3) * 8;
            uint4 v = *(const uint4*)(Ag + (size_t)r * 512 + kc + c8);
            *(uint4*)(As + r * AS_STRIDE + c8) = v;
        }
#pragma unroll
        for (int t = 0; t < 2; t++) {
            int id = tid + t * 256;
            int r = id >> 4, c8 = (id & 15) * 8;
            if (F32ACT) {
                float4 v0 = *(const float4*)(Bg32 + (size_t)(kc + r) * 4096 + c8);
                float4 v1 = *(const float4*)(Bg32 + (size_t)(kc + r) * 4096 + c8 + 4);
                __nv_bfloat162 p0 = __floats2bfloat162_rn(v0.x, v0.y);
                __nv_bfloat162 p1 = __floats2bfloat162_rn(v0.z, v0.w);
                __nv_bfloat162 p2 = __floats2bfloat162_rn(v1.x, v1.y);
                __nv_bfloat162 p3 = __floats2bfloat162_rn(v1.z, v1.w);
                uint4 pk;
                pk.x = *(uint32_t*)&p0; pk.y = *(uint32_t*)&p1;
                pk.z = *(uint32_t*)&p2; pk.w = *(uint32_t*)&p3;
                *(uint4*)(Bs + r * BS_STRIDE + c8) = pk;
            } else {
                uint4 v = *(const uint4*)(Bg16 + (size_t)(kc + r) * 4096 + c8);
                *(uint4*)(Bs + r * BS_STRIDE + c8) = v;
            }
        }
        __syncthreads();
#pragma unroll
        for (int ks = 0; ks < 2; ks++) {
            wmma::fragment<wmma::matrix_a, 16, 16, 16, __nv_bfloat16, wmma::row_major> af[2];
            wmma::fragment<wmma::matrix_b, 16, 16, 16, __nv_bfloat16, wmma::row_major> bf[4];
#pragma unroll
            for (int i = 0; i < 2; i++)
                wmma::load_matrix_sync(af[i], As + (wm*32 + i*16) * AS_STRIDE + ks*16, AS_STRIDE);
#pragma unroll
            for (int j = 0; j < 4; j++)
                wmma::load_matrix_sync(bf[j], Bs + (ks*16) * BS_STRIDE + wn*64 + j*16, BS_STRIDE);
#pragma unroll
            for (int i = 0; i < 2; i++)
#pragma unroll
                for (int j = 0; j < 4; j++)
                    wmma::mma_sync(acc[i][j], af[i], bf[j], acc[i][j]);
        }
    }
    __syncthreads();
#pragma unroll
    for (int i = 0; i < 2; i++)
#pragma unroll
        for (int j = 0; j < 4; j++)
            wmma::store_matrix_sync(Cs + (wm*32 + i*16) * CS_STRIDE + wn*64 + j*16,
                                    acc[i][j], CS_STRIDE, wmma::mem_row_major);
    __syncthreads();
#pragma unroll
    for (int t = 0; t < 16; t++) {
        int id = tid + t * 256;
        int r = id >> 5, c = (id & 31) * 4;
        float bi = bias ? bias[mb + r] : 0.0f;
        float4 v = *(float4*)(Cs + r * CS_STRIDE + c);
        v.x += bi; v.y += bi; v.z += bi; v.w += bi;
        size_t off = ((size_t)b * Mtot + mb + r) * 4096 + nb + c;
        if (resid) {
            float4 rr = *(const float4*)(resid + off);
            v.x += rr.x; v.y += rr.y; v.z += rr.z; v.w += rr.w;
        }
        *(float4*)(out + off) = v;
    }
}

// ---------------- conversion (weights only) ----------------
__global__ void __launch_bounds__(256) k_cvt(const float* __restrict__ src,
                                             __nv_bfloat16* __restrict__ dst, int n) {
    int i = (blockIdx.x * 256 + threadIdx.x) * 4;
    if (i < n) {
        float4 v = *(const float4*)(src + i);
        __nv_bfloat162 p0 = __floats2bfloat162_rn(v.x, v.y);
        __nv_bfloat162 p1 = __floats2bfloat162_rn(v.z, v.w);
        uint2 pk;
        pk.x = *(uint32_t*)&p0; pk.y = *(uint32_t*)&p1;
        *(uint2*)(dst + i) = pk;
    }
}

// ================= radix-4 FFT (64-pt, 3 stages, in-place smem) =================
template<int Q, int M>
__device__ __forceinline__ void fft4s_fwd(float* Ar, float* Ai,
                                          const float* twr, const float* twi,
                                          int tid, bool col) {
#pragma unroll
    for (int i = 0; i < 4; i++) {
        int t = tid + (i << 8);
        int line = t >> 4;
        int j16 = t & 15;
        int blk = j16 / Q, j = j16 - blk * Q;
        int base = blk * (4 * Q) + j;
        int p0 = base, p1 = base + Q, p2 = base + 2*Q, p3 = base + 3*Q;
        int a0 = col ? p0*65 + line : line*65 + p0;
        int a1 = col ? p1*65 + line : line*65 + p1;
        int a2 = col ? p2*65 + line : line*65 + p2;
        int a3 = col ? p3*65 + line : line*65 + p3;
        float x0r=Ar[a0], x0i=Ai[a0], x1r=Ar[a1], x1i=Ai[a1];
        float x2r=Ar[a2], x2i=Ai[a2], x3r=Ar[a3], x3i=Ai[a3];
        float t0r=x0r+x2r, t0i=x0i+x2i;
        float t1r=x0r-x2r, t1i=x0i-x2i;
        float t2r=x1r+x3r, t2i=x1i+x3i;
        float t3r=x1i-x3i, t3i=x3r-x1r;          // -i*(x1-x3)
        Ar[a0]=t0r+t2r; Ai[a0]=t0i+t2i;
        float w1r=twr[M*j],   w1i=twi[M*j];
        float w2r=twr[2*M*j], w2i=twi[2*M*j];
        float w3r=twr[3*M*j], w3i=twi[3*M*j];
        float u1r=t1r+t3r, u1i=t1i+t3i;
        Ar[a1]=u1r*w1r-u1i*w1i; Ai[a1]=u1r*w1i+u1i*w1r;
        float u2r=t0r-t2r, u2i=t0i-t2i;
        Ar[a2]=u2r*w2r-u2i*w2i; Ai[a2]=u2r*w2i+u2i*w2r;
        float u3r=t1r-t3r, u3i=t1i-t3i;
        Ar[a3]=u3r*w3r-u3i*w3i; Ai[a3]=u3r*w3i+u3i*w3r;
    }
}

template<int Q, int M>
__device__ __forceinline__ void fft4s_inv(float* Ar, float* Ai,
                                          const float* twr, const float* twi,
                                          int tid, bool col) {
#pragma unroll
    for (int i = 0; i < 4; i++) {
        int t = tid + (i << 8);
        int line = t >> 4;
        int j16 = t & 15;
        int blk = j16 / Q, j = j16 - blk * Q;
        int base = blk * (4 * Q) + j;
        int p0 = base, p1 = base + Q, p2 = base + 2*Q, p3 = base + 3*Q;
        int a0 = col ? p0*65 + line : line*65 + p0;
        int a1 = col ? p1*65 + line : line*65 + p1;
        int a2 = col ? p2*65 + line : line*65 + p2;
        int a3 = col ? p3*65 + line : line*65 + p3;
        float u0r=Ar[a0], u0i=Ai[a0];
        float v1r=Ar[a1], v1i=Ai[a1];
        float v2r=Ar[a2], v2i=Ai[a2];
        float v3r=Ar[a3], v3i=Ai[a3];
        float w1r=twr[M*j],   w1i=twi[M*j];
        float w2r=twr[2*M*j], w2i=twi[2*M*j];
        float w3r=twr[3*M*j], w3i=twi[3*M*j];
        float b1r=v1r*w1r+v1i*w1i, b1i=v1i*w1r-v1r*w1i;
        float b2r=v2r*w2r+v2i*w2i, b2i=v2i*w2r-v2r*w2i;
        float b3r=v3r*w3r+v3i*w3i, b3i=v3i*w3r-v3r*w3i;
        float s0r=u0r+b2r, s0i=u0i+b2i;
        float s1r=u0r-b2r, s1i=u0i-b2i;
        float s2r=b1r+b3r, s2i=b1i+b3i;
        float s3r=b3i-b1i, s3i=b1r-b3r;          // +i*(b1-b3)
        Ar[a0]=s0r+s2r; Ai[a0]=s0i+s2i;
        Ar[a1]=s1r+s3r; Ai[a1]=s1i+s3i;
        Ar[a2]=s0r-s2r; Ai[a2]=s0i-s2i;
        Ar[a3]=s1r-s3r; Ai[a3]=s1i-s3i;
    }
}

__device__ __forceinline__ void fft4_fwd_dim(float* Ar, float* Ai,
                                             const float* twr, const float* twi,
                                             int tid, bool col) {
    fft4s_fwd<16,1>(Ar, Ai, twr, twi, tid, col); __syncthreads();
    fft4s_fwd<4,4> (Ar, Ai, twr, twi, tid, col); __syncthreads();
    fft4s_fwd<1,16>(Ar, Ai, twr, twi, tid, col); __syncthreads();
}

__device__ __forceinline__ void fft4_inv_dim(float* Ar, float* Ai,
                                             const float* twr, const float* twi,
                                             int tid, bool col) {
    fft4s_inv<1,16>(Ar, Ai, twr, twi, tid, col); __syncthreads();
    fft4s_inv<4,4> (Ar, Ai, twr, twi, tid, col); __syncthreads();
    fft4s_inv<16,1>(Ar, Ai, twr, twi, tid, col); __syncthreads();
}

__device__ __forceinline__ void fft_load_tw64(float* twr, float* twi, int tid) {
    if (tid < 64) {
        float s, c;
        sincosf(-6.28318530717958647692f * (float)tid * (1.0f/64.0f), &s, &c);
        twr[tid] = c; twi[tid] = s;
    }
}

// ---------------- K2: fused depthwise 3x3 + BN + ReLU + stats + forward FFT ----
__global__ void __launch_bounds__(256) k_dwfft(const float* __restrict__ dww,
                                               const float* __restrict__ dwb,
                                               const float* __restrict__ gamma,
                                               const float* __restrict__ beta,
                                               const float* __restrict__ mean,
                                               const float* __restrict__ var) {
    __shared__ float Abuf[66*66];        // halo tile, then reused as Ar[64*65]
    __shared__ float Ai[64*65];
    __shared__ float twr[64], twi[64];
    __shared__ float rs[8], rq[8];
    int plane = blockIdx.x;
    int c = plane & (MIDC-1);
    int tid = threadIdx.x;
    const float* src = g_buf1 + (size_t)plane*HW;
    for (int idx = tid; idx < 66*66; idx += 256) {
        int r = idx / 66, cc = idx - r*66;
        int y = r - 1, x = cc - 1;
        float v = 0.f;
        if ((unsigned)y < 64u && (unsigned)x < 64u) v = src[y*64 + x];
        Abuf[idx] = v;
    }
    fft_load_tw64(twr, twi, tid);
    __syncthreads();
    float w0 = dww[c*9+0], w1 = dww[c*9+1], w2 = dww[c*9+2];
    float w3 = dww[c*9+3], w4 = dww[c*9+4], w5 = dww[c*9+5];
    float w6 = dww[c*9+6], w7 = dww[c*9+7], w8 = dww[c*9+8];
    float scale = gamma[c] * rsqrtf(var[c] + 1e-5f);
    float shift = beta[c] - mean[c]*scale;
    float bia = dwb[c];
    float xr[16];
    float s = 0.f, sq = 0.f;
#pragma unroll
    for (int i = 0; i < 16; i++) {
        int p = tid + i*256;
        int py = p >> 6, px = p & 63;
        const float* t0 = &Abuf[py*66 + px];
        float acc = t0[0]*w0 + t0[1]*w1 + t0[2]*w2
                  + t0[66]*w3 + t0[67]*w4 + t0[68]*w5
                  + t0[132]*w6 + t0[133]*w7 + t0[134]*w8;
        acc = fmaxf((acc + bia)*scale + shift, 0.f);
        xr[i] = acc; s += acc; sq += acc*acc;
    }
    __syncthreads();   // everyone done reading the tile
#pragma unroll
    for (int i = 0; i < 16; i++) {
        int p = tid + i*256; int r = p >> 6, cc = p & 63;
        Abuf[r*65 + cc] = xr[i];
        Ai[r*65 + cc] = 0.f;
    }
#pragma unroll
    for (int o = 16; o; o >>= 1) {
        s  += __shfl_xor_sync(0xffffffffu, s,  o);
        sq += __shfl_xor_sync(0xffffffffu, sq, o);
    }
    int wid = tid >> 5;
    if ((tid & 31) == 0) { rs[wid] = s; rq[wid] = sq; }
    __syncthreads();
    if (tid == 0) {
        float ts = 0.f, tq = 0.f;
#pragma unroll
        for (int w = 0; w < 8; w++) { ts += rs[w]; tq += rq[w]; }
        g_means[plane] = ts * (1.f/4096.f);
        g_nrm[plane]   = sqrtf(tq);   // Parseval: ||F||2 == ||xr||2 (ortho)
    }
    fft4_fwd_dim(Abuf, Ai, twr, twi, tid, false);
    fft4_fwd_dim(Abuf, Ai, twr, twi, tid, true);
    __half* fr = g_Fr_h + (size_t)plane*HW;
    __half* fi = g_Fi_h + (size_t)plane*HW;
#pragma unroll
    for (int i = 0; i < 16; i++) {
        int p = tid + i*256; int r = p >> 6, cc = p & 63;
        fr[p] = __float2half(Abuf[r*65+cc] * (1.f/64.f));
        fi[p] = __float2half(Ai[r*65+cc] * (1.f/64.f));
    }
}

// ---------------- K3: SE gate MLP ----------------
__global__ void __launch_bounds__(256) k_gate(const float* __restrict__ w1,
                                              const float* __restrict__ b1,
                                              const float* __restrict__ w2,
                                              const float* __restrict__ b2) {
    int b = blockIdx.x;
    __shared__ float sm[MIDC];
    __shared__ float sh[32];
    int tid = threadIdx.x;
    sm[tid] = g_means[b*MIDC + tid];
    __syncthreads();
    if (tid < 32) {
        float a = b1[tid];
        const float* wr = w1 + tid*MIDC;
        for (int c2 = 0; c2 < MIDC; c2++) a += wr[c2]*sm[c2];
        sh[tid] = fmaxf(a, 0.f);
    }
    __syncthreads();
    float a = b2[tid];
    const float* wr = w2 + tid*32;
#pragma unroll
    for (int j = 0; j < 32; j++) a += wr[j]*sh[j];
    g_gate[b*MIDC + tid] = 1.f / (1.f + expf(-a));
}

// ---------------- K4a: partial Grams, 8 n-slices per (b,h) ----------------
__global__ void __launch_bounds__(256) k_gram() {
    int s = blockIdx.x, h = blockIdx.y, b = blockIdx.z;
    size_t base = ((size_t)b*MIDC + h*32) * HW + s*512;
    __shared__ float sFr[32][65], sFi[32][65];
    __shared__ float sRed[4][1024];
    int tid = threadIdx.x;
    int nsub = tid >> 6;
    int tt = tid & 63;
    int c0 = (tt >> 3) * 4, d0 = (tt & 7) * 4;
    float acc[4][4] = {};
    for (int n0 = 0; n0 < 512; n0 += 64) {
        __syncthreads();
        for (int idx = tid; idx < 2048; idx += 256) {
            int cc = idx >> 6, nn = idx & 63;
            sFr[cc][nn] = __half2float(g_Fr_h[base + (size_t)cc*HW + n0 + nn]);
            sFi[cc][nn] = __half2float(g_Fi_h[base + (size_t)cc*HW + n0 + nn]);
        }
        __syncthreads();
        int nlo = nsub * 16;
#pragma unroll 4
        for (int nn = nlo; nn < nlo + 16; nn++) {
            float rc[4], ic[4], rd[4], jd[4];
#pragma unroll
            for (int i = 0; i < 4; i++) { rc[i] = sFr[c0+i][nn]; ic[i] = sFi[c0+i][nn]; }
#pragma unroll
            for (int j = 0; j < 4; j++) { rd[j] = sFr[d0+j][nn]; jd[j] = sFi[d0+j][nn]; }
#pragma unroll
            for (int i = 0; i < 4; i++)
#pragma unroll
                for (int j = 0; j < 4; j++)
                    acc[i][j] += rc[i]*rd[j] - ic[i]*jd[j];
        }
    }
#pragma unroll
    for (int i = 0; i < 4; i++)
#pragma unroll
        for (int j = 0; j < 4; j++)
            sRed[nsub][tt*16 + i*4 + j] = acc[i][j];
    __syncthreads();
    float* part = g_gram_part + ((size_t)(b*HEADS + h)*8 + s)*1024;
#pragma unroll
    for (int q = 0; q < 4; q++) {
        int e = tid*4 + q;
        int te = e >> 4, sub = e & 15;
        int i = sub >> 2, j = sub & 3;
        int c = (te >> 3)*4 + i, d = (te & 7)*4 + j;
        part[c*32 + d] = sRed[0][e] + sRed[1][e] + sRed[2][e] + sRed[3][e];
    }
}

// ---------------- K4b: reduce partials + normalize + softmax ----------------
__global__ void __launch_bounds__(256) k_soft(const float* __restrict__ temp) {
    int h = blockIdx.x, b = blockIdx.y;
    __shared__ float sA[32][33], sN[32];
    int tid = threadIdx.x;
    if (tid < 32) sN[tid] = fmaxf(g_nrm[b*MIDC + h*32 + tid], 1e-12f);
    __syncthreads();
    float tK = temp[h];
    const float* part = g_gram_part + (size_t)(b*HEADS + h)*8*1024;
#pragma unroll
    for (int q = 0; q < 4; q++) {
        int e = tid*4 + q;
        int c = e >> 5, d = e & 31;
        float v = 0.f;
#pragma unroll
        for (int s = 0; s < 8; s++) v += part[s*1024 + e];
        sA[c][d] = v * tK / (sN[c] * sN[d]);
    }
    __syncthreads();
    int lane = tid & 31;
    float* aw = g_attnW + (size_t)(b*HEADS + h)*1024;
#pragma unroll
    for (int rr = 0; rr < 4; rr++) {
        int row = (tid >> 5)*4 + rr;
        float v = sA[row][lane];
        float mx = v;
#pragma unroll
        for (int o = 16; o; o >>= 1) mx = fmaxf(mx, __shfl_xor_sync(0xffffffffu, mx, o));
        float e = expf(v - mx);
        float smv = e;
#pragma unroll
        for (int o = 16; o; o >>= 1) smv += __shfl_xor_sync(0xffffffffu, smv, o);
        aw[row*32 + lane] = e / smv;
    }
}

// ---------------- K4c: mix out[c,n] = sum_d attn[c,d]*Fr[d,n], 8 n-slices ------
__global__ void __launch_bounds__(256) k_mix() {
    int s = blockIdx.x, h = blockIdx.y, b = blockIdx.z;
    size_t base = ((size_t)b*MIDC + h*32) * HW + s*512;
    __shared__ float sA[32][33];
    __shared__ float sFr[32][65];
    int tid = threadIdx.x;
    const float* aw = g_attnW + (size_t)(b*HEADS + h)*1024;
#pragma unroll
    for (int q = 0; q < 4; q++) {
        int e = tid*4 + q;
        sA[e >> 5][e & 31] = aw[e];
    }
    int cm = (tid >> 4) * 2;
    int nm = (tid & 15) * 4;
    for (int n0 = 0; n0 < 512; n0 += 64) {
        __syncthreads();
        for (int idx = tid; idx < 2048; idx += 256) {
            int cc = idx >> 6, nn = idx & 63;
            sFr[cc][nn] = __half2float(g_Fr_h[base + (size_t)cc*HW + n0 + nn]);
        }
        __syncthreads();
        float o0[4] = {}, o1[4] = {};
#pragma unroll
        for (int d = 0; d < 32; d++) {
            float a0 = sA[cm][d], a1 = sA[cm+1][d];
            float f0 = sFr[d][nm], f1 = sFr[d][nm+1], f2 = sFr[d][nm+2], f3 = sFr[d][nm+3];
            o0[0] += a0*f0; o0[1] += a0*f1; o0[2] += a0*f2; o0[3] += a0*f3;
            o1[0] += a1*f0; o1[1] += a1*f1; o1[2] += a1*f2; o1[3] += a1*f3;
        }
        __half2 q00 = __floats2half2_rn(o0[0], o0[1]);
        __half2 q01 = __floats2half2_rn(o0[2], o0[3]);
        __half2 q10 = __floats2half2_rn(o1[0], o1[1]);
        __half2 q11 = __floats2half2_rn(o1[2], o1[3]);
        uint2 pk0, pk1;
        pk0.x = *(uint32_t*)&q00; pk0.y = *(uint32_t*)&q01;
        pk1.x = *(uint32_t*)&q10; pk1.y = *(uint32_t*)&q11;
        *(uint2*)&g_mix_h[base + (size_t)cm*HW + n0 + nm]     = pk0;
        *(uint2*)&g_mix_h[base + (size_t)(cm+1)*HW + n0 + nm] = pk1;
    }
}

// ---------------- K6: inverse FFT (ortho) of attn branch -> fused_bf[:, 0:256] ------
__global__ void __launch_bounds__(256) k_ifft_attn() {
    __shared__ float Ar[64*65], Ai[64*65], twr[64], twi[64];
    int plane = blockIdx.x, tid = threadIdx.x;
    int b = plane >> 8, c = plane & (MIDC-1);
    const __half* src = g_mix_h + (size_t)plane*HW;
#pragma unroll
    for (int i = 0; i < 16; i++) {
        int p = tid + i*256; int r = p >> 6, cc = p & 63;
        Ar[r*65+cc] = __half2float(src[p]); Ai[r*65+cc] = 0.f;
    }
    fft_load_tw64(twr, twi, tid);
    __syncthreads();
    fft4_inv_dim(Ar, Ai, twr, twi, tid, false);
    fft4_inv_dim(Ar, Ai, twr, twi, tid, true);
    __nv_bfloat16* dst = g_fused_bf + ((size_t)b*INDIM + c)*HW;
#pragma unroll
    for (int i = 0; i < 16; i++) {
        int p = tid + i*256; int r = p >> 6, cc = p & 63;
        dst[p] = __float2bfloat16(Ar[r*65+cc] * (1.f/64.f));   // ortho ifft2
    }
}

// ---------------- K7: fwm = (g/64) * IDFT(F^2) -> fused_bf[:, 256:512] ----------
__global__ void __launch_bounds__(256) k_fwm() {
    __shared__ float Ar[64*65], Ai[64*65], twr[64], twi[64];
    int plane = blockIdx.x, tid = threadIdx.x;
    int b = plane >> 8, c = plane & (MIDC-1);
    const __half* fr = g_Fr_h + (size_t)plane*HW;
    const __half* fi = g_Fi_h + (size_t)plane*HW;
#pragma unroll
    for (int i = 0; i < 16; i++) {
        int p = tid + i*256; int r = p >> 6, cc = p & 63;
        float xr_ = __half2float(fr[p]), xi_ = __half2float(fi[p]);
        Ar[r*65+cc] = xr_*xr_ - xi_*xi_;
        Ai[r*65+cc] = 2.f * xr_ * xi_;
    }
    fft_load_tw64(twr, twi, tid);
    __syncthreads();
    fft4_inv_dim(Ar, Ai, twr, twi, tid, false);
    fft4_inv_dim(Ar, Ai, twr, twi, tid, true);
    float sc = g_gate[b*MIDC + c] * (1.f/64.f);
    __nv_bfloat16* dst = g_fused_bf + ((size_t)b*INDIM + MIDC + c)*HW;
#pragma unroll
    for (int i = 0; i < 16; i++) {
        int p = tid + i*256; int r = p >> 6, cc = p & 63;
        dst[p] = __float2bfloat16(Ar[r*65+cc] * sc);
    }
}

// ---------------- launch ----------------
extern "C" void kernel_launch(void* const* d_in, const int* in_sizes, int n_in,
                              void* d_out, int out_size) {
    (void)in_sizes; (void)n_in; (void)out_size;
    const float* x        = (const float*)d_in[0];
    const float* reduce_w = (const float*)d_in[1];
    const float* reduce_b = (const float*)d_in[2];
    const float* dw_w     = (const float*)d_in[3];
    const float* dw_b     = (const float*)d_in[4];
    const float* bn_gamma = (const float*)d_in[5];
    const float* bn_beta  = (const float*)d_in[6];
    const float* bn_mean  = (const float*)d_in[7];
    const float* bn_var   = (const float*)d_in[8];
    const float* gate_w1  = (const float*)d_in[9];
    const float* gate_b1  = (const float*)d_in[10];
    const float* gate_w2  = (const float*)d_in[11];
    const float* gate_b2  = (const float*)d_in[12];
    const float* temp     = (const float*)d_in[13];
    const float* post_w   = (const float*)d_in[14];
    const float* post_b   = (const float*)d_in[15];
    float* out = (float*)d_out;

    cudaFuncSetAttribute(k_wmma_gemm<true>,  cudaFuncAttributeMaxDynamicSharedMemorySize, GEMM_SMEM);
    cudaFuncSetAttribute(k_wmma_gemm<false>, cudaFuncAttributeMaxDynamicSharedMemorySize, GEMM_SMEM);

    __nv_bfloat16 *p_fbf, *p_wred, *p_wpost;
    cudaGetSymbolAddress((void**)&p_fbf,   g_fused_bf);
    cudaGetSymbolAddress((void**)&p_wred,  g_wred);
    cudaGetSymbolAddress((void**)&p_wpost, g_wpost);
    float* p_buf1;
    cudaGetSymbolAddress((void**)&p_buf1, g_buf1);

    // weight conversions (small)
    k_cvt<<<(MIDC*INDIM/4 + 255)/256, 256>>>(reduce_w, p_wred, MIDC*INDIM);
    k_cvt<<<(INDIM*2*MIDC/4 + 255)/256, 256>>>(post_w, p_wpost, INDIM*2*MIDC);

    // reduce GEMM: [256,4096] = W[256,512] * x[512,4096] + reduce_b (x read fp32)
    k_wmma_gemm<true><<<dim3(32, 2, BATCH), 256, GEMM_SMEM>>>(
        p_wred, x, reduce_b, nullptr, p_buf1, MIDC);

    // fused dw + BN + ReLU + stats + forward FFT -> F (fp16, digit-rev)
    k_dwfft<<<BATCH*MIDC, 256>>>(dw_w, dw_b, bn_gamma, bn_beta, bn_mean, bn_var);
    k_gate<<<BATCH, 256>>>(gate_w1, gate_b1, gate_w2, gate_b2);

    // attention: partial Grams -> softmax -> mix
    k_gram<<<dim3(8, HEADS, BATCH), 256>>>();
    k_soft<<<dim3(HEADS, BATCH), 256>>>(temp);
    k_mix<<<dim3(8, HEADS, BATCH), 256>>>();

    k_ifft_attn<<<BATCH*MIDC, 256>>>();
    k_fwm<<<BATCH*MIDC, 256>>>();

    // post GEMM: [512,4096] = W[512,512] * fused[512,4096] + post_b + x
    k_wmma_gemm<false><<<dim3(32, 4, BATCH), 256, GEMM_SMEM>>>(
        p_wpost, p_fbf, post_b, x, out, INDIM);
}